// round 7
// baseline (speedup 1.0000x reference)
#include <cuda_runtime.h>

typedef unsigned long long u64;
typedef unsigned int u32;

#define BD   32
#define LD   513
#define DD   8
#define HD   64
#define WINW 16
#define NW   32
#define OUTD 4
#define NPAIR 28
#define NTH  1024

// ---- smem layout (float offsets; all 16B-aligned) ----
#define OFF_W1B  0        // uint4[8*128]  bf16: W1B[b8*128+r]  = bf16(W1[r][8b8..+7])
#define OFF_W2B  4096     // uint4[16*128] bf16: W2B[r8*128+k]  = bf16(W2[k][8r8..+7])
#define OFF_W3B  12288    // uint4[16*512] bf16: W3B[q8*512+row]= bf16(W3[row][8q8..+7])
#define OFF_G    45056    // 1152
#define OFF_Y    46208
#define OFF_YMID 46272
#define OFF_K1   46336
#define OFF_CM   46400
#define OFF_H1   46464
#define OFF_S1   46592
#define OFF_H2   46720
#define OFF_S2   46848
#define OFF_F    46976    // 512
#define OFF_TP   47488    // 512
#define OFF_VPT  48000    // 512
#define OFF_D1F  48512    // 1024
#define OFF_PART 49536    // 4096 (sEF aliases chunk 0; P7 partials at +1024; sInc at init)
#define OFF_B1   53632    // 128
#define OFF_B2   53760    // 128
#define OFF_B3   53888    // 512
#define OFF_WR   54400    // 256
#define OFF_BR   54656    // 4
#define OFF_SHIFT 54660
#define SMEM_FLOATS 54664 // 218,656 B

__device__ const signed char PI_[NPAIR] = {0,0,0,0,0,0,0, 1,1,1,1,1,1, 2,2,2,2,2, 3,3,3,3, 4,4,4, 5,5, 6};
__device__ const signed char PJ_[NPAIR] = {1,2,3,4,5,6,7, 2,3,4,5,6,7, 3,4,5,6,7, 4,5,6,7, 5,6,7, 6,7, 7};

// ---------- fast math ----------
__device__ __forceinline__ float ex2f(float x){ float y; asm("ex2.approx.f32 %0, %1;" : "=f"(y) : "f"(x)); return y; }
__device__ __forceinline__ float rcpf(float x){ float y; asm("rcp.approx.f32 %0, %1;" : "=f"(y) : "f"(x)); return y; }
__device__ __forceinline__ float sigf(float x){ return rcpf(1.0f + ex2f(-1.4426950408889634f * x)); }
__device__ __forceinline__ float tanh_fast(float x){
    float t = ex2f(2.8853900817779268f * x);
    return 1.0f - 2.0f * rcpf(t + 1.0f);
}
__device__ __forceinline__ float lipswish(float x, float* dout){
    float s = sigf(x);
    *dout = 0.909f * s * fmaf(x, 1.0f - s, 1.0f);
    return 0.909f * x * s;
}

// ---------- bf16 ----------
__device__ __forceinline__ u32 pk_bf16(float lo, float hi){
    u32 r; asm("cvt.rn.bf16x2.f32 %0, %1, %2;" : "=r"(r) : "f"(hi), "f"(lo)); return r;
}
__device__ __forceinline__ float lo2f(u32 w){ return __uint_as_float(w << 16); }
__device__ __forceinline__ float hi2f(u32 w){ return __uint_as_float(w & 0xffff0000u); }

__device__ __forceinline__ void bf8_fma(float& a0, float& a1, uint4 w, float4 ha, float4 hb){
    a0 = fmaf(lo2f(w.x), ha.x, a0); a1 = fmaf(hi2f(w.x), ha.y, a1);
    a0 = fmaf(lo2f(w.y), ha.z, a0); a1 = fmaf(hi2f(w.y), ha.w, a1);
    a0 = fmaf(lo2f(w.z), hb.x, a0); a1 = fmaf(hi2f(w.z), hb.y, a1);
    a0 = fmaf(lo2f(w.w), hb.z, a0); a1 = fmaf(hi2f(w.w), hb.w, a1);
}

__device__ __forceinline__ int pidx(int i, int j) { return (i * (13 - i)) / 2 + j - 1; }

extern __shared__ float sm[];

// PH=1: writes sk1, symid.  PH=2: updates sy.
template<int PH>
__device__ __forceinline__ void vf_apply(int tid, const float* __restrict__ yv,
                                         const float* __restrict__ gvec, float dt)
{
    const uint4* W1B = (const uint4*)(sm + OFF_W1B);
    const uint4* W2B = (const uint4*)(sm + OFF_W2B);
    const uint4* W3B = (const uint4*)(sm + OFF_W3B);
    float* sh1 = sm + OFF_H1;  float* ss1 = sm + OFF_S1;
    float* sh2 = sm + OFF_H2;  float* ss2 = sm + OFF_S2;
    float* sf  = sm + OFF_F;   float* stp = sm + OFF_TP;
    float* sVpT = sm + OFF_VPT; float* sD1F = sm + OFF_D1F;
    float* sPart = sm + OFF_PART;
    float* sEF = sm + OFF_PART;           // alias: chunk 0
    const float* scm = sm + OFF_CM;

    const int r = tid & 127;       // row/col for 128-wide phases
    const int c8 = tid >> 7;       // 8-way chunk id

    // ---- P1p: L1 forward partials (1024 threads; b8 = c8) ----
    {
        float a0 = 0.f, a1 = 0.f;
        uint4 w = W1B[c8 * 128 + r];
        float4 ya = *(const float4*)(yv + 8 * c8);
        float4 yb = *(const float4*)(yv + 8 * c8 + 4);
        bf8_fma(a0, a1, w, ya, yb);
        sPart[c8 * 128 + r] = a0 + a1;
    }
    __syncthreads();

    // ---- P1r: reduce -> sh1, ss1 (128 threads) ----
    if (tid < 128) {
        float s = sm[OFF_B1 + tid];
        #pragma unroll
        for (int c = 0; c < 8; c++) s += sPart[c * 128 + tid];
        float d; sh1[tid] = lipswish(s, &d); ss1[tid] = d;
    }
    __syncthreads();

    // ---- P2p: L2 forward partials (1024 threads; r8 = 2c8, 2c8+1) ----
    {
        float a0 = 0.f, a1 = 0.f;
        #pragma unroll
        for (int i = 0; i < 2; i++){
            const int r8 = 2 * c8 + i;
            uint4 w = W2B[r8 * 128 + r];
            float4 ha = *(const float4*)(sh1 + 8 * r8);
            float4 hb = *(const float4*)(sh1 + 8 * r8 + 4);
            bf8_fma(a0, a1, w, ha, hb);
        }
        sPart[c8 * 128 + r] = a0 + a1;
    }
    __syncthreads();

    // ---- P2r: reduce -> sh2, ss2 (128 threads) ----
    if (tid < 128) {
        float s = sm[OFF_B2 + tid];
        #pragma unroll
        for (int c = 0; c < 8; c++) s += sPart[c * 128 + tid];
        float d; sh2[tid] = lipswish(s, &d); ss2[tid] = d;
    }
    __syncthreads();

    // ---- P3p: L3 forward partials (1024 threads; h = K-half, row = tid&511) ----
    {
        const int h = tid >> 9, row = tid & 511;
        float a0 = 0.f, a1 = 0.f;
        #pragma unroll
        for (int i = 0; i < 8; i++){
            const int q8 = h * 8 + i;
            uint4 w = W3B[q8 * 512 + row];
            float4 ha = *(const float4*)(sh2 + 8 * q8);
            float4 hb = *(const float4*)(sh2 + 8 * q8 + 4);
            bf8_fma(a0, a1, w, ha, hb);
        }
        sPart[h * 512 + row] = a0 + a1;
    }
    __syncthreads();

    // ---- P3r: f = tanh(pre), tp (512 threads) ----
    if (tid < 512) {
        float f = tanh_fast(sm[OFF_B3 + tid] + sPart[tid] + sPart[512 + tid]);
        sf[tid] = f;
        stp[tid] = 1.0f - f * f;
    }
    __syncthreads();

    // ---- P4: VpT[j][b] = sum_i f[i*64+b] * cmat[i][j] (512 threads) ----
    if (tid < 512) {
        const int j = tid >> 6, bq = tid & 63;
        float acc = 0.f;
        #pragma unroll
        for (int i = 0; i < 8; i++) acc += sf[i * 64 + bq] * scm[i * 8 + j];
        sVpT[j * 64 + bq] = acc;
    }
    __syncthreads();

    // ---- P5p: U1' partials (1024 threads; bc = b-chunk(4), hj = j-half) ----
    {
        const int bc = c8 & 3, hj = c8 >> 2;
        float acc[4] = {0,0,0,0};
        #pragma unroll
        for (int ib = 0; ib < 2; ib++){
            const int b8 = 2 * bc + ib;
            uint4 w = W1B[b8 * 128 + r];
            float w0 = lo2f(w.x), w1 = hi2f(w.x), w2 = lo2f(w.y), w3 = hi2f(w.y);
            float w4 = lo2f(w.z), w5 = hi2f(w.z), w6 = lo2f(w.w), w7 = hi2f(w.w);
            #pragma unroll
            for (int jj = 0; jj < 4; jj++){
                const int j = 4 * hj + jj;
                float4 d0 = *(const float4*)(sVpT + j * 64 + 8 * b8);
                float4 d1 = *(const float4*)(sVpT + j * 64 + 8 * b8 + 4);
                float t = acc[jj];
                t = fmaf(w0, d0.x, t); t = fmaf(w1, d0.y, t);
                t = fmaf(w2, d0.z, t); t = fmaf(w3, d0.w, t);
                t = fmaf(w4, d1.x, t); t = fmaf(w5, d1.y, t);
                t = fmaf(w6, d1.z, t); t = fmaf(w7, d1.w, t);
                acc[jj] = t;
            }
        }
        #pragma unroll
        for (int jj = 0; jj < 4; jj++)
            sPart[bc * 1024 + (4 * hj + jj) * 128 + r] = acc[jj];
    }
    __syncthreads();

    // ---- P5b: U1' reduce -> D1F[j][r] (512 threads: 4 j-groups x 128) ----
    if (tid < 512) {
        const int jg = tid >> 7;
        const float s = ss1[r];
        #pragma unroll
        for (int jj = jg; jj < 8; jj += 4){
            float v = sPart[jj * 128 + r] + sPart[1024 + jj * 128 + r]
                    + sPart[2048 + jj * 128 + r] + sPart[3072 + jj * 128 + r];
            sD1F[jj * 128 + r] = s * v;
        }
    }
    __syncthreads();

    // ---- P6p: U2' partials (1024 threads; rc = r-chunk(4), hj = j-half) ----
    {
        const int rc = c8 & 3, hj = c8 >> 2;
        float acc[4] = {0,0,0,0};
        #pragma unroll
        for (int ir = 0; ir < 4; ir++){
            const int r8 = 4 * rc + ir;
            uint4 w = W2B[r8 * 128 + r];
            float w0 = lo2f(w.x), w1 = hi2f(w.x), w2 = lo2f(w.y), w3 = hi2f(w.y);
            float w4 = lo2f(w.z), w5 = hi2f(w.z), w6 = lo2f(w.w), w7 = hi2f(w.w);
            #pragma unroll
            for (int jj = 0; jj < 4; jj++){
                const int j = 4 * hj + jj;
                float4 d0 = *(const float4*)(sD1F + j * 128 + 8 * r8);
                float4 d1 = *(const float4*)(sD1F + j * 128 + 8 * r8 + 4);
                float t = acc[jj];
                t = fmaf(w0, d0.x, t); t = fmaf(w1, d0.y, t);
                t = fmaf(w2, d0.z, t); t = fmaf(w3, d0.w, t);
                t = fmaf(w4, d1.x, t); t = fmaf(w5, d1.y, t);
                t = fmaf(w6, d1.z, t); t = fmaf(w7, d1.w, t);
                acc[jj] = t;
            }
        }
        #pragma unroll
        for (int jj = 0; jj < 4; jj++)
            sPart[rc * 1024 + (4 * hj + jj) * 128 + r] = acc[jj];
    }
    __syncthreads();

    // ---- P6b: U2' reduce -> EF[j][k] (aliases sPart chunk 0) ----
    if (tid < 512) {
        const int jg = tid >> 7;
        const float s = ss2[r];
        #pragma unroll
        for (int jj = jg; jj < 8; jj += 4){
            float v = sPart[jj * 128 + r] + sPart[1024 + jj * 128 + r]
                    + sPart[2048 + jj * 128 + r] + sPart[3072 + jj * 128 + r];
            sEF[jj * 128 + r] = s * v;
        }
    }
    __syncthreads();

    // ---- P7p: diag partials (1024 threads; h = K-half; partials at sPart+1024) ----
    {
        const int h = tid >> 9, row = tid & 511, j = row >> 6;
        const float* Ej = sEF + j * 128;
        float a0 = 0.f, a1 = 0.f;
        #pragma unroll
        for (int i = 0; i < 8; i++){
            const int q8 = h * 8 + i;
            uint4 w = W3B[q8 * 512 + row];
            float4 ea = *(const float4*)(Ej + 8 * q8);
            float4 eb = *(const float4*)(Ej + 8 * q8 + 4);
            bf8_fma(a0, a1, w, ea, eb);
        }
        sPart[1024 + h * 512 + row] = a0 + a1;
    }
    __syncthreads();

    // ---- P8: combine (folds P7 reduce + stp) + Heun update (64 threads) ----
    if (tid < 64){
        float acc = 0.f;
        #pragma unroll
        for (int j = 0; j < 8; j++){
            const int row = j * 64 + tid;
            acc += stp[row] * (sPart[1024 + row] + sPart[1536 + row]);
        }
        #pragma unroll
        for (int i = 0; i < 8; i++) acc += gvec[i] * sf[i * 64 + tid];
        if (PH == 1){
            sm[OFF_K1 + tid] = acc;
            sm[OFF_YMID + tid] = sm[OFF_Y + tid] + dt * acc;
        } else {
            sm[OFF_Y + tid] = sm[OFF_Y + tid] + 0.5f * dt * (sm[OFF_K1 + tid] + acc);
        }
    }
    __syncthreads();
}

__global__ void __launch_bounds__(NTH, 1) ncde_kernel(
    const float* __restrict__ cv,
    const float* __restrict__ Wi1, const float* __restrict__ bi1,
    const float* __restrict__ Wi2, const float* __restrict__ bi2,
    const float* __restrict__ W1, const float* __restrict__ b1,
    const float* __restrict__ W2, const float* __restrict__ b2,
    const float* __restrict__ W3, const float* __restrict__ b3,
    const float* __restrict__ Wr, const float* __restrict__ br,
    const float* __restrict__ shiftp,
    float* __restrict__ out)
{
    const int tid = threadIdx.x;
    const int b = blockIdx.x;

    const float dt = (float)WINW / (float)(LD - 1);
    const float inv_dt = 1.0f / dt;

    uint4* W1B = (uint4*)(sm + OFF_W1B);
    uint4* W2B = (uint4*)(sm + OFF_W2B);
    uint4* W3B = (uint4*)(sm + OFF_W3B);
    float* sG = sm + OFF_G;
    float* sInc = sm + OFF_PART;

    // ---- init: pack weights bf16, increments, small params ----
    for (int idx = tid; idx < 8 * 128; idx += NTH){
        int b8 = idx >> 7, r = idx & 127;
        float4 a = ((const float4*)W1)[r * 16 + 2 * b8];
        float4 c4 = ((const float4*)W1)[r * 16 + 2 * b8 + 1];
        uint4 w;
        w.x = pk_bf16(a.x, a.y);   w.y = pk_bf16(a.z, a.w);
        w.z = pk_bf16(c4.x, c4.y); w.w = pk_bf16(c4.z, c4.w);
        W1B[idx] = w;
    }
    for (int idx = tid; idx < 16 * 128; idx += NTH){
        int r8 = idx >> 7, k = idx & 127;
        float4 a = ((const float4*)W2)[k * 32 + 2 * r8];
        float4 c4 = ((const float4*)W2)[k * 32 + 2 * r8 + 1];
        uint4 w;
        w.x = pk_bf16(a.x, a.y);   w.y = pk_bf16(a.z, a.w);
        w.z = pk_bf16(c4.x, c4.y); w.w = pk_bf16(c4.z, c4.w);
        W2B[idx] = w;
    }
    for (int idx = tid; idx < 16 * 512; idx += NTH){
        int q8 = idx >> 9, row = idx & 511;
        float4 a = ((const float4*)W3)[row * 32 + 2 * q8];
        float4 c4 = ((const float4*)W3)[row * 32 + 2 * q8 + 1];
        uint4 w;
        w.x = pk_bf16(a.x, a.y);   w.y = pk_bf16(a.z, a.w);
        w.z = pk_bf16(c4.x, c4.y); w.w = pk_bf16(c4.z, c4.w);
        W3B[idx] = w;
    }
    const float* cvb = cv + (size_t)b * LD * DD;
    for (int idx = tid; idx < 512 * 8; idx += NTH){
        sInc[idx] = cvb[idx + 8] - cvb[idx];
    }
    if (tid < 128) sm[OFF_B1 + tid] = b1[tid];
    else if (tid < 256) sm[OFF_B2 + tid - 128] = b2[tid - 128];
    else if (tid < 260) sm[OFF_BR + tid - 256] = br[tid - 256];
    else if (tid == 260) sm[OFF_SHIFT] = *shiftp;
    for (int idx = tid; idx < 512; idx += NTH) sm[OFF_B3 + idx] = b3[idx];
    for (int idx = tid; idx < 256; idx += NTH) sm[OFF_WR + idx] = Wr[idx];
    __syncthreads();

    // ---- window log-signatures (pre-divided by dt) + y0 layer 1 ----
    for (int idx = tid; idx < NW * NPAIR; idx += NTH){
        int w = idx / NPAIR, p = idx % NPAIR;
        int i = PI_[p], j = PJ_[p];
        float acc = 0.f, pi = 0.f, pj = 0.f;
        const float* base = sInc + w * 16 * 8;
        #pragma unroll
        for (int s = 0; s < 16; s++){
            float ii = base[s * 8 + i], jj = base[s * 8 + j];
            acc += pi * jj - pj * ii;
            pi += ii; pj += jj;
        }
        sG[w * 36 + 8 + p] = 0.5f * acc * inv_dt;
    }
    for (int idx = tid; idx < NW * 8; idx += NTH){
        int w = idx >> 3, d2 = idx & 7;
        sG[w * 36 + d2] = (cvb[(16 * w + 16) * 8 + d2] - cvb[16 * w * 8 + d2]) * inv_dt;
    }
    if (tid < 64){
        float acc = bi1[tid];
        #pragma unroll
        for (int d2 = 0; d2 < 8; d2++) acc += Wi1[tid * 8 + d2] * cvb[d2];
        float dd; sm[OFF_H1 + tid] = lipswish(acc, &dd);
    }
    __syncthreads();
    if (tid < 64){
        float acc = bi2[tid];
        #pragma unroll 8
        for (int h = 0; h < 64; h++) acc += Wi2[tid * 64 + h] * sm[OFF_H1 + h];
        sm[OFF_Y + tid] = acc;
    }
    __syncthreads();

    // ---- main Heun loop ----
    for (int n = 0; n < NW; n++){
        const float* gvec = sG + n * 36;
        // head (no own barrier: covered by P1p's barrier inside vf_apply;
        // scm consumed at P4, out/y reads race-free in this epoch)
        if (tid >= 512 && tid < 576){
            int t = tid - 512;
            int i = t >> 3, j = t & 7;
            float v = 0.0f;
            if (i < j) v = gvec[8 + pidx(i, j)];
            else if (i > j) v = -gvec[8 + pidx(j, i)];
            sm[OFF_CM + t] = v;
        } else if (tid >= 576 && tid < 580){
            int o = tid - 576;
            float acc = sm[OFF_BR + o] + sm[OFF_SHIFT];
            #pragma unroll 8
            for (int a = 0; a < 64; a++) acc += sm[OFF_WR + o * 64 + a] * sm[OFF_Y + a];
            out[b * (NW + 1) * OUTD + n * OUTD + o] = acc;
        }

        vf_apply<1>(tid, sm + OFF_Y,    gvec, dt);
        vf_apply<2>(tid, sm + OFF_YMID, gvec, dt);
    }

    // final readout (index NW)
    if (tid < 4){
        float acc = sm[OFF_BR + tid] + sm[OFF_SHIFT];
        #pragma unroll 8
        for (int a = 0; a < 64; a++) acc += sm[OFF_WR + tid * 64 + a] * sm[OFF_Y + a];
        out[b * (NW + 1) * OUTD + NW * OUTD + tid] = acc;
    }
}

extern "C" void kernel_launch(void* const* d_in, const int* in_sizes, int n_in,
                              void* d_out, int out_size) {
    (void)in_sizes; (void)n_in; (void)out_size;
    const size_t smem = SMEM_FLOATS * sizeof(float);  // 218,656 B
    cudaFuncSetAttribute(ncde_kernel, cudaFuncAttributeMaxDynamicSharedMemorySize, (int)smem);
    ncde_kernel<<<BD, NTH, smem>>>(
        (const float*)d_in[0],
        (const float*)d_in[1], (const float*)d_in[2],
        (const float*)d_in[3], (const float*)d_in[4],
        (const float*)d_in[5], (const float*)d_in[6],
        (const float*)d_in[7], (const float*)d_in[8],
        (const float*)d_in[9], (const float*)d_in[10],
        (const float*)d_in[11], (const float*)d_in[12],
        (const float*)d_in[13],
        (float*)d_out);
}

// round 8
// speedup vs baseline: 1.0386x; 1.0386x over previous
#include <cuda_runtime.h>

typedef unsigned long long u64;
typedef unsigned int u32;

#define BD   32
#define LD   513
#define DD   8
#define HD   64
#define WINW 16
#define NW   32
#define OUTD 4
#define NPAIR 28
#define NTH  512

// ---- smem layout (float offsets; all 16B-aligned) ----
#define OFF_W1B  0        // uint4[8*128]  bf16: W1B[b8*128+r]  = bf16(W1[r][8b8..+7])
#define OFF_W2B  4096     // uint4[16*128] bf16: W2B[r8*128+k]  = bf16(W2[k][8r8..+7])
#define OFF_W3B  12288    // uint4[16*512] bf16: W3B[q8*512+row]= bf16(W3[row][8q8..+7])
#define OFF_G    45056    // 1152
#define OFF_Y    46208
#define OFF_YMID 46272
#define OFF_K1   46336
#define OFF_CM   46400
#define OFF_H1   46464
#define OFF_S1   46592
#define OFF_H2   46720
#define OFF_S2   46848
#define OFF_F    46976    // 512
#define OFF_VPT  47488    // 512 (sp aliases: VpT dead after P5, sp born at P7)
#define OFF_SP   47488
#define OFF_D1F  48000    // 1024
#define OFF_PART 49024    // 4096 (sEF aliases chunk 0; sInc staging at init)
#define OFF_B1   53120    // 128
#define OFF_B2   53248    // 128
#define OFF_B3   53376    // 512
#define OFF_WR   53888    // 256
#define OFF_BR   54144    // 4
#define OFF_SHIFT 54148
#define SMEM_FLOATS 54152 // 216,608 B

__device__ const signed char PI_[NPAIR] = {0,0,0,0,0,0,0, 1,1,1,1,1,1, 2,2,2,2,2, 3,3,3,3, 4,4,4, 5,5, 6};
__device__ const signed char PJ_[NPAIR] = {1,2,3,4,5,6,7, 2,3,4,5,6,7, 3,4,5,6,7, 4,5,6,7, 5,6,7, 6,7, 7};

// ---------- fast math ----------
__device__ __forceinline__ float ex2f(float x){ float y; asm("ex2.approx.f32 %0, %1;" : "=f"(y) : "f"(x)); return y; }
__device__ __forceinline__ float rcpf(float x){ float y; asm("rcp.approx.f32 %0, %1;" : "=f"(y) : "f"(x)); return y; }
__device__ __forceinline__ float sigf(float x){ return rcpf(1.0f + ex2f(-1.4426950408889634f * x)); }
__device__ __forceinline__ float tanh_fast(float x){
    float t = ex2f(2.8853900817779268f * x);
    return 1.0f - 2.0f * rcpf(t + 1.0f);
}
__device__ __forceinline__ float lipswish(float x, float* dout){
    float s = sigf(x);
    *dout = 0.909f * s * fmaf(x, 1.0f - s, 1.0f);
    return 0.909f * x * s;
}

// ---------- bf16 ----------
__device__ __forceinline__ u32 pk_bf16(float lo, float hi){
    u32 r; asm("cvt.rn.bf16x2.f32 %0, %1, %2;" : "=r"(r) : "f"(hi), "f"(lo)); return r;
}
__device__ __forceinline__ float lo2f(u32 w){ return __uint_as_float(w << 16); }
__device__ __forceinline__ float hi2f(u32 w){ return __uint_as_float(w & 0xffff0000u); }

__device__ __forceinline__ void bf8_fma(float& a0, float& a1, uint4 w, float4 ha, float4 hb){
    a0 = fmaf(lo2f(w.x), ha.x, a0); a1 = fmaf(hi2f(w.x), ha.y, a1);
    a0 = fmaf(lo2f(w.y), ha.z, a0); a1 = fmaf(hi2f(w.y), ha.w, a1);
    a0 = fmaf(lo2f(w.z), hb.x, a0); a1 = fmaf(hi2f(w.z), hb.y, a1);
    a0 = fmaf(lo2f(w.w), hb.z, a0); a1 = fmaf(hi2f(w.w), hb.w, a1);
}

__device__ __forceinline__ int pidx(int i, int j) { return (i * (13 - i)) / 2 + j - 1; }

extern __shared__ float sm[];

// PH=1: writes sk1, symid.  PH=2: updates sy.
template<int PH>
__device__ __forceinline__ void vf_apply(int tid, const float* __restrict__ yv,
                                         const float* __restrict__ gvec, float dt)
{
    const uint4* W1B = (const uint4*)(sm + OFF_W1B);
    const uint4* W2B = (const uint4*)(sm + OFF_W2B);
    const uint4* W3B = (const uint4*)(sm + OFF_W3B);
    float* sh1 = sm + OFF_H1;  float* ss1 = sm + OFF_S1;
    float* sh2 = sm + OFF_H2;  float* ss2 = sm + OFF_S2;
    float* sf  = sm + OFF_F;
    float* sVpT = sm + OFF_VPT; float* sD1F = sm + OFF_D1F;
    float* sPart = sm + OFF_PART;
    float* sEF = sm + OFF_PART;           // alias: chunk 0
    float* sp = sm + OFF_SP;              // alias: VpT
    const float* scm = sm + OFF_CM;

    // ---- P1: L1 forward (128 threads) ----
    if (tid < 128) {
        const int r = tid;
        float a0 = 0.f, a1 = 0.f;
        #pragma unroll
        for (int b8 = 0; b8 < 8; b8++){
            uint4 w = W1B[b8 * 128 + r];
            float4 ya = *(const float4*)(yv + 8 * b8);
            float4 yb = *(const float4*)(yv + 8 * b8 + 4);
            bf8_fma(a0, a1, w, ya, yb);
        }
        float d; sh1[r] = lipswish(sm[OFF_B1 + r] + a0 + a1, &d); ss1[r] = d;
    }
    __syncthreads();

    // ---- P2: L2 forward (128 threads) ----
    if (tid < 128) {
        const int k = tid;
        float a0 = 0.f, a1 = 0.f;
        #pragma unroll 4
        for (int r8 = 0; r8 < 16; r8++){
            uint4 w = W2B[r8 * 128 + k];
            float4 ha = *(const float4*)(sh1 + 8 * r8);
            float4 hb = *(const float4*)(sh1 + 8 * r8 + 4);
            bf8_fma(a0, a1, w, ha, hb);
        }
        float d; sh2[k] = lipswish(sm[OFF_B2 + k] + a0 + a1, &d); ss2[k] = d;
    }
    __syncthreads();

    // ---- P3: L3 forward (512 threads, row = tid, full K=128) ----
    {
        const int row = tid;
        float a0 = 0.f, a1 = 0.f;
        #pragma unroll 4
        for (int q8 = 0; q8 < 16; q8++){
            uint4 w = W3B[q8 * 512 + row];
            float4 ha = *(const float4*)(sh2 + 8 * q8);
            float4 hb = *(const float4*)(sh2 + 8 * q8 + 4);
            bf8_fma(a0, a1, w, ha, hb);
        }
        sf[row] = tanh_fast(sm[OFF_B3 + row] + a0 + a1);
    }
    __syncthreads();

    // ---- P4: VpT[j][b] = sum_i f[i*64+b] * cmat[i][j] ----
    {
        const int j = tid >> 6, bq = tid & 63;
        float acc = 0.f;
        #pragma unroll
        for (int i = 0; i < 8; i++) acc += sf[i * 64 + bq] * scm[i * 8 + j];
        sVpT[j * 64 + bq] = acc;
    }
    __syncthreads();

    // ---- P5: U1' merged (512 threads; r = tid&127, jg = tid>>7 handles j=jg, jg+4) ----
    {
        const int r = tid & 127, jg = tid >> 7;
        float acc0 = 0.f, acc1 = 0.f;
        const float* v0 = sVpT + jg * 64;
        const float* v1 = sVpT + (jg + 4) * 64;
        #pragma unroll
        for (int b8 = 0; b8 < 8; b8++){
            uint4 w = W1B[b8 * 128 + r];
            float4 a0q = *(const float4*)(v0 + 8 * b8);
            float4 a1q = *(const float4*)(v0 + 8 * b8 + 4);
            bf8_fma(acc0, acc0, w, a0q, a1q);
            float4 b0q = *(const float4*)(v1 + 8 * b8);
            float4 b1q = *(const float4*)(v1 + 8 * b8 + 4);
            bf8_fma(acc1, acc1, w, b0q, b1q);
        }
        const float s = ss1[r];
        sD1F[jg * 128 + r]       = s * acc0;
        sD1F[(jg + 4) * 128 + r] = s * acc1;
    }
    __syncthreads();

    // ---- P6p: U2' partials (512 threads; c = chunk over r, k = tid&127) ----
    {
        const int c = tid >> 7, k = tid & 127;
        float acc[8] = {0,0,0,0,0,0,0,0};
        #pragma unroll
        for (int ir = 0; ir < 4; ir++){
            const int r8 = 4 * c + ir;
            uint4 w = W2B[r8 * 128 + k];
            float w0 = lo2f(w.x), w1 = hi2f(w.x), w2 = lo2f(w.y), w3 = hi2f(w.y);
            float w4 = lo2f(w.z), w5 = hi2f(w.z), w6 = lo2f(w.w), w7 = hi2f(w.w);
            #pragma unroll
            for (int j = 0; j < 8; j++){
                float4 d0 = *(const float4*)(sD1F + j * 128 + 8 * r8);
                float4 d1 = *(const float4*)(sD1F + j * 128 + 8 * r8 + 4);
                float t = acc[j];
                t = fmaf(w0, d0.x, t); t = fmaf(w1, d0.y, t);
                t = fmaf(w2, d0.z, t); t = fmaf(w3, d0.w, t);
                t = fmaf(w4, d1.x, t); t = fmaf(w5, d1.y, t);
                t = fmaf(w6, d1.z, t); t = fmaf(w7, d1.w, t);
                acc[j] = t;
            }
        }
        #pragma unroll
        for (int j = 0; j < 8; j++) sPart[c * 1024 + j * 128 + k] = acc[j];
    }
    __syncthreads();

    // ---- P6b: U2' reduce -> EF[j][k] (sEF aliases sPart chunk 0) ----
    {
        const int jg = tid >> 7, k = tid & 127;
        const float s = ss2[k];
        #pragma unroll
        for (int jj = jg; jj < 8; jj += 4){
            float v = sPart[jj * 128 + k] + sPart[1024 + jj * 128 + k]
                    + sPart[2048 + jj * 128 + k] + sPart[3072 + jj * 128 + k];
            sEF[jj * 128 + k] = s * v;
        }
    }
    __syncthreads();

    // ---- P7: diag + folded g-term (row = tid, j = row>>6, full K=128) ----
    {
        const int row = tid, j = row >> 6;
        const float* Ej = sEF + j * 128;
        float a0 = 0.f, a1 = 0.f;
        #pragma unroll 4
        for (int q8 = 0; q8 < 16; q8++){
            uint4 w = W3B[q8 * 512 + row];
            float4 ea = *(const float4*)(Ej + 8 * q8);
            float4 eb = *(const float4*)(Ej + 8 * q8 + 4);
            bf8_fma(a0, a1, w, ea, eb);
        }
        float f = sf[row];
        sp[row] = (1.0f - f * f) * (a0 + a1) + gvec[j] * f;   // sp aliases VpT (dead)
    }
    __syncthreads();

    // ---- P8: combine + Heun update (64 threads) ----
    if (tid < 64){
        float acc = 0.f;
        #pragma unroll
        for (int j = 0; j < 8; j++) acc += sp[j * 64 + tid];
        if (PH == 1){
            sm[OFF_K1 + tid] = acc;
            sm[OFF_YMID + tid] = sm[OFF_Y + tid] + dt * acc;
        } else {
            sm[OFF_Y + tid] = sm[OFF_Y + tid] + 0.5f * dt * (sm[OFF_K1 + tid] + acc);
        }
    }
    __syncthreads();
}

__global__ void __launch_bounds__(NTH, 1) ncde_kernel(
    const float* __restrict__ cv,
    const float* __restrict__ Wi1, const float* __restrict__ bi1,
    const float* __restrict__ Wi2, const float* __restrict__ bi2,
    const float* __restrict__ W1, const float* __restrict__ b1,
    const float* __restrict__ W2, const float* __restrict__ b2,
    const float* __restrict__ W3, const float* __restrict__ b3,
    const float* __restrict__ Wr, const float* __restrict__ br,
    const float* __restrict__ shiftp,
    float* __restrict__ out)
{
    const int tid = threadIdx.x;
    const int b = blockIdx.x;

    const float dt = (float)WINW / (float)(LD - 1);
    const float inv_dt = 1.0f / dt;

    uint4* W1B = (uint4*)(sm + OFF_W1B);
    uint4* W2B = (uint4*)(sm + OFF_W2B);
    uint4* W3B = (uint4*)(sm + OFF_W3B);
    float* sG = sm + OFF_G;
    float* sInc = sm + OFF_PART;

    // ---- init: pack weights bf16, increments, small params ----
    for (int idx = tid; idx < 8 * 128; idx += NTH){
        int b8 = idx >> 7, r = idx & 127;
        float4 a = ((const float4*)W1)[r * 16 + 2 * b8];
        float4 c4 = ((const float4*)W1)[r * 16 + 2 * b8 + 1];
        uint4 w;
        w.x = pk_bf16(a.x, a.y);   w.y = pk_bf16(a.z, a.w);
        w.z = pk_bf16(c4.x, c4.y); w.w = pk_bf16(c4.z, c4.w);
        W1B[idx] = w;
    }
    for (int idx = tid; idx < 16 * 128; idx += NTH){
        int r8 = idx >> 7, k = idx & 127;
        float4 a = ((const float4*)W2)[k * 32 + 2 * r8];
        float4 c4 = ((const float4*)W2)[k * 32 + 2 * r8 + 1];
        uint4 w;
        w.x = pk_bf16(a.x, a.y);   w.y = pk_bf16(a.z, a.w);
        w.z = pk_bf16(c4.x, c4.y); w.w = pk_bf16(c4.z, c4.w);
        W2B[idx] = w;
    }
    for (int idx = tid; idx < 16 * 512; idx += NTH){
        int q8 = idx >> 9, row = idx & 511;
        float4 a = ((const float4*)W3)[row * 32 + 2 * q8];
        float4 c4 = ((const float4*)W3)[row * 32 + 2 * q8 + 1];
        uint4 w;
        w.x = pk_bf16(a.x, a.y);   w.y = pk_bf16(a.z, a.w);
        w.z = pk_bf16(c4.x, c4.y); w.w = pk_bf16(c4.z, c4.w);
        W3B[idx] = w;
    }
    const float* cvb = cv + (size_t)b * LD * DD;
    for (int idx = tid; idx < 512 * 8; idx += NTH){
        sInc[idx] = cvb[idx + 8] - cvb[idx];
    }
    if (tid < 128) sm[OFF_B1 + tid] = b1[tid];
    else if (tid < 256) sm[OFF_B2 + tid - 128] = b2[tid - 128];
    else if (tid < 260) sm[OFF_BR + tid - 256] = br[tid - 256];
    else if (tid == 260) sm[OFF_SHIFT] = *shiftp;
    for (int idx = tid; idx < 512; idx += NTH) sm[OFF_B3 + idx] = b3[idx];
    for (int idx = tid; idx < 256; idx += NTH) sm[OFF_WR + idx] = Wr[idx];
    __syncthreads();

    // ---- window log-signatures (pre-divided by dt) + y0 layer 1 ----
    for (int idx = tid; idx < NW * NPAIR; idx += NTH){
        int w = idx / NPAIR, p = idx % NPAIR;
        int i = PI_[p], j = PJ_[p];
        float acc = 0.f, pi = 0.f, pj = 0.f;
        const float* base = sInc + w * 16 * 8;
        #pragma unroll
        for (int s = 0; s < 16; s++){
            float ii = base[s * 8 + i], jj = base[s * 8 + j];
            acc += pi * jj - pj * ii;
            pi += ii; pj += jj;
        }
        sG[w * 36 + 8 + p] = 0.5f * acc * inv_dt;
    }
    for (int idx = tid; idx < NW * 8; idx += NTH){
        int w = idx >> 3, d2 = idx & 7;
        sG[w * 36 + d2] = (cvb[(16 * w + 16) * 8 + d2] - cvb[16 * w * 8 + d2]) * inv_dt;
    }
    if (tid < 64){
        float acc = bi1[tid];
        #pragma unroll
        for (int d2 = 0; d2 < 8; d2++) acc += Wi1[tid * 8 + d2] * cvb[d2];
        float dd; sm[OFF_H1 + tid] = lipswish(acc, &dd);
    }
    __syncthreads();
    if (tid < 64){
        float acc = bi2[tid];
        #pragma unroll 8
        for (int h = 0; h < 64; h++) acc += Wi2[tid * 64 + h] * sm[OFF_H1 + h];
        sm[OFF_Y + tid] = acc;
    }
    __syncthreads();

    // ---- main Heun loop ----
    for (int n = 0; n < NW; n++){
        const float* gvec = sG + n * 36;
        // head: folded into P1 epoch (threads 128-195; no own barrier —
        // scm consumed at P4 (3 barriers later); sy stable during PH1)
        if (tid >= 128 && tid < 192){
            int t = tid - 128;
            int i = t >> 3, j = t & 7;
            float v = 0.0f;
            if (i < j) v = gvec[8 + pidx(i, j)];
            else if (i > j) v = -gvec[8 + pidx(j, i)];
            sm[OFF_CM + t] = v;
        } else if (tid >= 192 && tid < 196){
            int o = tid - 192;
            float acc = sm[OFF_BR + o] + sm[OFF_SHIFT];
            #pragma unroll 8
            for (int a = 0; a < 64; a++) acc += sm[OFF_WR + o * 64 + a] * sm[OFF_Y + a];
            out[b * (NW + 1) * OUTD + n * OUTD + o] = acc;
        }

        vf_apply<1>(tid, sm + OFF_Y,    gvec, dt);
        vf_apply<2>(tid, sm + OFF_YMID, gvec, dt);
    }

    // final readout (index NW)
    if (tid < 4){
        float acc = sm[OFF_BR + tid] + sm[OFF_SHIFT];
        #pragma unroll 8
        for (int a = 0; a < 64; a++) acc += sm[OFF_WR + tid * 64 + a] * sm[OFF_Y + a];
        out[b * (NW + 1) * OUTD + NW * OUTD + tid] = acc;
    }
}

extern "C" void kernel_launch(void* const* d_in, const int* in_sizes, int n_in,
                              void* d_out, int out_size) {
    (void)in_sizes; (void)n_in; (void)out_size;
    const size_t smem = SMEM_FLOATS * sizeof(float);  // 216,608 B
    cudaFuncSetAttribute(ncde_kernel, cudaFuncAttributeMaxDynamicSharedMemorySize, (int)smem);
    ncde_kernel<<<BD, NTH, smem>>>(
        (const float*)d_in[0],
        (const float*)d_in[1], (const float*)d_in[2],
        (const float*)d_in[3], (const float*)d_in[4],
        (const float*)d_in[5], (const float*)d_in[6],
        (const float*)d_in[7], (const float*)d_in[8],
        (const float*)d_in[9], (const float*)d_in[10],
        (const float*)d_in[11], (const float*)d_in[12],
        (const float*)d_in[13],
        (float*)d_out);
}

// round 9
// speedup vs baseline: 1.0668x; 1.0271x over previous
#include <cuda_runtime.h>

typedef unsigned long long u64;
typedef unsigned int u32;

#define BD   32
#define LD   513
#define DD   8
#define HD   64
#define WINW 16
#define NW   32
#define OUTD 4
#define NPAIR 28
#define NTH  512

// ---- smem layout (float offsets; all 16B-aligned) ----
#define OFF_W1B  0        // uint4[8*128]  bf16: W1B[b8*128+r]  = bf16(W1[r][8b8..+7])
#define OFF_W2B  4096     // uint4[16*128] bf16: W2B[r8*128+k]  = bf16(W2[k][8r8..+7])
#define OFF_W3B  12288    // uint4[16*512] bf16: W3B[q8*512+row]= bf16(W3[row][8q8..+7])
#define OFF_G    45056    // 1152
#define OFF_Y    46208
#define OFF_YMID 46272
#define OFF_K1   46336
#define OFF_CM   46400
#define OFF_H1   46464
#define OFF_S1   46592
#define OFF_H2   46720
#define OFF_S2   46848
#define OFF_F    46976    // 512
#define OFF_VPT  47488    // 512 (sp aliases: VpT dead after P5, sp born at P7)
#define OFF_SP   47488
#define OFF_D1F  48000    // 1024
#define OFF_PART 49024    // 4096 (sEF aliases chunk 0; sInc staging at init)
#define OFF_B1   53120    // 128
#define OFF_B2   53248    // 128
#define OFF_B3   53376    // 512
#define OFF_WR   53888    // 256
#define OFF_BR   54144    // 4
#define OFF_SHIFT 54148
#define SMEM_FLOATS 54152 // 216,608 B

__device__ const signed char PI_[NPAIR] = {0,0,0,0,0,0,0, 1,1,1,1,1,1, 2,2,2,2,2, 3,3,3,3, 4,4,4, 5,5, 6};
__device__ const signed char PJ_[NPAIR] = {1,2,3,4,5,6,7, 2,3,4,5,6,7, 3,4,5,6,7, 4,5,6,7, 5,6,7, 6,7, 7};

// ---------- fast math ----------
__device__ __forceinline__ float ex2f(float x){ float y; asm("ex2.approx.f32 %0, %1;" : "=f"(y) : "f"(x)); return y; }
__device__ __forceinline__ float rcpf(float x){ float y; asm("rcp.approx.f32 %0, %1;" : "=f"(y) : "f"(x)); return y; }
__device__ __forceinline__ float sigf(float x){ return rcpf(1.0f + ex2f(-1.4426950408889634f * x)); }
__device__ __forceinline__ float tanh_fast(float x){
    float t = ex2f(2.8853900817779268f * x);
    return 1.0f - 2.0f * rcpf(t + 1.0f);
}
__device__ __forceinline__ float lipswish(float x, float* dout){
    float s = sigf(x);
    *dout = 0.909f * s * fmaf(x, 1.0f - s, 1.0f);
    return 0.909f * x * s;
}

// ---------- bf16 / f32x2 helpers ----------
__device__ __forceinline__ u32 pk_bf16(float lo, float hi){
    u32 r; asm("cvt.rn.bf16x2.f32 %0, %1, %2;" : "=r"(r) : "f"(hi), "f"(lo)); return r;
}
// (w_even, w_odd) packed bf16x2 -> f32x2 u64. lo = exact (x<<16); hi = raw x
// (junk low mantissa, rel err <= 2^-7 ~ bf16 rounding level).
__device__ __forceinline__ u64 wpair(u32 x){
    u64 v; asm("mov.b64 %0, {%1, %2};" : "=l"(v) : "r"(x << 16), "r"(x)); return v;
}
__device__ __forceinline__ u64 fma2(u64 a, u64 b, u64 c){
    u64 d; asm("fma.rn.f32x2 %0, %1, %2, %3;" : "=l"(d) : "l"(a), "l"(b), "l"(c)); return d;
}
__device__ __forceinline__ float hsum2(u64 v){
    float a, b; asm("mov.b64 {%0, %1}, %2;" : "=f"(a), "=f"(b) : "l"(v)); return a + b;
}

__device__ __forceinline__ int pidx(int i, int j) { return (i * (13 - i)) / 2 + j - 1; }

extern __shared__ float sm[];

// dot of 8 bf16 weights (uint4) with 8 fp32 acts (2x ulonglong2) into 2 f32x2 accs
__device__ __forceinline__ void w8_fma2(u64& a0, u64& a1, uint4 w,
                                        ulonglong2 ha, ulonglong2 hb){
    a0 = fma2(wpair(w.x), ha.x, a0);
    a1 = fma2(wpair(w.y), ha.y, a1);
    a0 = fma2(wpair(w.z), hb.x, a0);
    a1 = fma2(wpair(w.w), hb.y, a1);
}

// PH=1: writes sk1, symid.  PH=2: updates sy.
template<int PH>
__device__ __forceinline__ void vf_apply(int tid, const float* __restrict__ yv,
                                         const float* __restrict__ gvec, float dt)
{
    const uint4* W1B = (const uint4*)(sm + OFF_W1B);
    const uint4* W2B = (const uint4*)(sm + OFF_W2B);
    const uint4* W3B = (const uint4*)(sm + OFF_W3B);
    float* sh1 = sm + OFF_H1;  float* ss1 = sm + OFF_S1;
    float* sh2 = sm + OFF_H2;  float* ss2 = sm + OFF_S2;
    float* sf  = sm + OFF_F;
    float* sVpT = sm + OFF_VPT; float* sD1F = sm + OFF_D1F;
    float* sPart = sm + OFF_PART;
    float* sEF = sm + OFF_PART;           // alias: chunk 0
    float* sp = sm + OFF_SP;              // alias: VpT
    const float* scm = sm + OFF_CM;

    // ---- P1: L1 forward (128 threads) ----
    if (tid < 128) {
        const int r = tid;
        u64 a0 = 0ull, a1 = 0ull;
        #pragma unroll
        for (int b8 = 0; b8 < 8; b8++){
            uint4 w = W1B[b8 * 128 + r];
            ulonglong2 ya = *(const ulonglong2*)(yv + 8 * b8);
            ulonglong2 yb = *(const ulonglong2*)(yv + 8 * b8 + 4);
            w8_fma2(a0, a1, w, ya, yb);
        }
        float pre = sm[OFF_B1 + r] + hsum2(a0) + hsum2(a1);
        float d; sh1[r] = lipswish(pre, &d); ss1[r] = d;
    }
    __syncthreads();

    // ---- P2: L2 forward (128 threads) ----
    if (tid < 128) {
        const int k = tid;
        u64 a0 = 0ull, a1 = 0ull;
        #pragma unroll 4
        for (int r8 = 0; r8 < 16; r8++){
            uint4 w = W2B[r8 * 128 + k];
            ulonglong2 ha = *(const ulonglong2*)(sh1 + 8 * r8);
            ulonglong2 hb = *(const ulonglong2*)(sh1 + 8 * r8 + 4);
            w8_fma2(a0, a1, w, ha, hb);
        }
        float pre = sm[OFF_B2 + k] + hsum2(a0) + hsum2(a1);
        float d; sh2[k] = lipswish(pre, &d); ss2[k] = d;
    }
    __syncthreads();

    // ---- P3: L3 forward (512 threads, row = tid, full K=128) ----
    {
        const int row = tid;
        u64 a0 = 0ull, a1 = 0ull;
        #pragma unroll 4
        for (int q8 = 0; q8 < 16; q8++){
            uint4 w = W3B[q8 * 512 + row];
            ulonglong2 ha = *(const ulonglong2*)(sh2 + 8 * q8);
            ulonglong2 hb = *(const ulonglong2*)(sh2 + 8 * q8 + 4);
            w8_fma2(a0, a1, w, ha, hb);
        }
        sf[row] = tanh_fast(sm[OFF_B3 + row] + hsum2(a0) + hsum2(a1));
    }
    __syncthreads();

    // ---- P4: VpT[j][b] = sum_i f[i*64+b] * cmat[i][j] ----
    {
        const int j = tid >> 6, bq = tid & 63;
        float acc = 0.f;
        #pragma unroll
        for (int i = 0; i < 8; i++) acc += sf[i * 64 + bq] * scm[i * 8 + j];
        sVpT[j * 64 + bq] = acc;
    }
    __syncthreads();

    // ---- P5: U1' merged (512 threads; r = tid&127, jg = tid>>7: j = jg, jg+4) ----
    {
        const int r = tid & 127, jg = tid >> 7;
        const float* v0 = sVpT + jg * 64;
        const float* v1 = sVpT + (jg + 4) * 64;
        u64 a00 = 0ull, a01 = 0ull, a10 = 0ull, a11 = 0ull;
        #pragma unroll
        for (int b8 = 0; b8 < 8; b8++){
            uint4 w = W1B[b8 * 128 + r];
            u64 p0 = wpair(w.x), p1 = wpair(w.y), p2 = wpair(w.z), p3 = wpair(w.w);
            ulonglong2 aa = *(const ulonglong2*)(v0 + 8 * b8);
            ulonglong2 ab = *(const ulonglong2*)(v0 + 8 * b8 + 4);
            a00 = fma2(p0, aa.x, a00); a01 = fma2(p1, aa.y, a01);
            a00 = fma2(p2, ab.x, a00); a01 = fma2(p3, ab.y, a01);
            ulonglong2 ba = *(const ulonglong2*)(v1 + 8 * b8);
            ulonglong2 bb = *(const ulonglong2*)(v1 + 8 * b8 + 4);
            a10 = fma2(p0, ba.x, a10); a11 = fma2(p1, ba.y, a11);
            a10 = fma2(p2, bb.x, a10); a11 = fma2(p3, bb.y, a11);
        }
        const float s = ss1[r];
        sD1F[jg * 128 + r]       = s * (hsum2(a00) + hsum2(a01));
        sD1F[(jg + 4) * 128 + r] = s * (hsum2(a10) + hsum2(a11));
    }
    __syncthreads();

    // ---- P6p: U2' partials (512 threads; c = chunk over r, k = tid&127) ----
    {
        const int c = tid >> 7, k = tid & 127;
        u64 acc[8] = {0ull,0ull,0ull,0ull,0ull,0ull,0ull,0ull};
        #pragma unroll
        for (int ir = 0; ir < 4; ir++){
            const int r8 = 4 * c + ir;
            uint4 w = W2B[r8 * 128 + k];
            u64 p0 = wpair(w.x), p1 = wpair(w.y), p2 = wpair(w.z), p3 = wpair(w.w);
            #pragma unroll
            for (int j = 0; j < 8; j++){
                ulonglong2 d0 = *(const ulonglong2*)(sD1F + j * 128 + 8 * r8);
                ulonglong2 d1 = *(const ulonglong2*)(sD1F + j * 128 + 8 * r8 + 4);
                u64 t = acc[j];
                t = fma2(p0, d0.x, t); t = fma2(p1, d0.y, t);
                t = fma2(p2, d1.x, t); t = fma2(p3, d1.y, t);
                acc[j] = t;
            }
        }
        #pragma unroll
        for (int j = 0; j < 8; j++) sPart[c * 1024 + j * 128 + k] = hsum2(acc[j]);
    }
    __syncthreads();

    // ---- P6b: U2' reduce -> EF[j][k] (sEF aliases sPart chunk 0) ----
    {
        const int jg = tid >> 7, k = tid & 127;
        const float s = ss2[k];
        #pragma unroll
        for (int jj = jg; jj < 8; jj += 4){
            float v = sPart[jj * 128 + k] + sPart[1024 + jj * 128 + k]
                    + sPart[2048 + jj * 128 + k] + sPart[3072 + jj * 128 + k];
            sEF[jj * 128 + k] = s * v;
        }
    }
    __syncthreads();

    // ---- P7: diag + folded g-term (row = tid, j = row>>6, full K=128) ----
    {
        const int row = tid, j = row >> 6;
        const float* Ej = sEF + j * 128;
        u64 a0 = 0ull, a1 = 0ull;
        #pragma unroll 4
        for (int q8 = 0; q8 < 16; q8++){
            uint4 w = W3B[q8 * 512 + row];
            ulonglong2 ea = *(const ulonglong2*)(Ej + 8 * q8);
            ulonglong2 eb = *(const ulonglong2*)(Ej + 8 * q8 + 4);
            w8_fma2(a0, a1, w, ea, eb);
        }
        float f = sf[row];
        sp[row] = (1.0f - f * f) * (hsum2(a0) + hsum2(a1)) + gvec[j] * f;
    }
    __syncthreads();

    // ---- P8: combine + Heun update (64 threads) ----
    if (tid < 64){
        float acc = 0.f;
        #pragma unroll
        for (int j = 0; j < 8; j++) acc += sp[j * 64 + tid];
        if (PH == 1){
            sm[OFF_K1 + tid] = acc;
            sm[OFF_YMID + tid] = sm[OFF_Y + tid] + dt * acc;
        } else {
            sm[OFF_Y + tid] = sm[OFF_Y + tid] + 0.5f * dt * (sm[OFF_K1 + tid] + acc);
        }
    }
    __syncthreads();
}

__global__ void __launch_bounds__(NTH, 1) ncde_kernel(
    const float* __restrict__ cv,
    const float* __restrict__ Wi1, const float* __restrict__ bi1,
    const float* __restrict__ Wi2, const float* __restrict__ bi2,
    const float* __restrict__ W1, const float* __restrict__ b1,
    const float* __restrict__ W2, const float* __restrict__ b2,
    const float* __restrict__ W3, const float* __restrict__ b3,
    const float* __restrict__ Wr, const float* __restrict__ br,
    const float* __restrict__ shiftp,
    float* __restrict__ out)
{
    const int tid = threadIdx.x;
    const int b = blockIdx.x;

    const float dt = (float)WINW / (float)(LD - 1);
    const float inv_dt = 1.0f / dt;

    uint4* W1B = (uint4*)(sm + OFF_W1B);
    uint4* W2B = (uint4*)(sm + OFF_W2B);
    uint4* W3B = (uint4*)(sm + OFF_W3B);
    float* sG = sm + OFF_G;
    float* sInc = sm + OFF_PART;

    // ---- init: pack weights bf16, increments, small params ----
    for (int idx = tid; idx < 8 * 128; idx += NTH){
        int b8 = idx >> 7, r = idx & 127;
        float4 a = ((const float4*)W1)[r * 16 + 2 * b8];
        float4 c4 = ((const float4*)W1)[r * 16 + 2 * b8 + 1];
        uint4 w;
        w.x = pk_bf16(a.x, a.y);   w.y = pk_bf16(a.z, a.w);
        w.z = pk_bf16(c4.x, c4.y); w.w = pk_bf16(c4.z, c4.w);
        W1B[idx] = w;
    }
    for (int idx = tid; idx < 16 * 128; idx += NTH){
        int r8 = idx >> 7, k = idx & 127;
        float4 a = ((const float4*)W2)[k * 32 + 2 * r8];
        float4 c4 = ((const float4*)W2)[k * 32 + 2 * r8 + 1];
        uint4 w;
        w.x = pk_bf16(a.x, a.y);   w.y = pk_bf16(a.z, a.w);
        w.z = pk_bf16(c4.x, c4.y); w.w = pk_bf16(c4.z, c4.w);
        W2B[idx] = w;
    }
    for (int idx = tid; idx < 16 * 512; idx += NTH){
        int q8 = idx >> 9, row = idx & 511;
        float4 a = ((const float4*)W3)[row * 32 + 2 * q8];
        float4 c4 = ((const float4*)W3)[row * 32 + 2 * q8 + 1];
        uint4 w;
        w.x = pk_bf16(a.x, a.y);   w.y = pk_bf16(a.z, a.w);
        w.z = pk_bf16(c4.x, c4.y); w.w = pk_bf16(c4.z, c4.w);
        W3B[idx] = w;
    }
    const float* cvb = cv + (size_t)b * LD * DD;
    for (int idx = tid; idx < 512 * 8; idx += NTH){
        sInc[idx] = cvb[idx + 8] - cvb[idx];
    }
    if (tid < 128) sm[OFF_B1 + tid] = b1[tid];
    else if (tid < 256) sm[OFF_B2 + tid - 128] = b2[tid - 128];
    else if (tid < 260) sm[OFF_BR + tid - 256] = br[tid - 256];
    else if (tid == 260) sm[OFF_SHIFT] = *shiftp;
    for (int idx = tid; idx < 512; idx += NTH) sm[OFF_B3 + idx] = b3[idx];
    for (int idx = tid; idx < 256; idx += NTH) sm[OFF_WR + idx] = Wr[idx];
    __syncthreads();

    // ---- window log-signatures (pre-divided by dt) + y0 layer 1 ----
    for (int idx = tid; idx < NW * NPAIR; idx += NTH){
        int w = idx / NPAIR, p = idx % NPAIR;
        int i = PI_[p], j = PJ_[p];
        float acc = 0.f, pi = 0.f, pj = 0.f;
        const float* base = sInc + w * 16 * 8;
        #pragma unroll
        for (int s = 0; s < 16; s++){
            float ii = base[s * 8 + i], jj = base[s * 8 + j];
            acc += pi * jj - pj * ii;
            pi += ii; pj += jj;
        }
        sG[w * 36 + 8 + p] = 0.5f * acc * inv_dt;
    }
    for (int idx = tid; idx < NW * 8; idx += NTH){
        int w = idx >> 3, d2 = idx & 7;
        sG[w * 36 + d2] = (cvb[(16 * w + 16) * 8 + d2] - cvb[16 * w * 8 + d2]) * inv_dt;
    }
    if (tid < 64){
        float acc = bi1[tid];
        #pragma unroll
        for (int d2 = 0; d2 < 8; d2++) acc += Wi1[tid * 8 + d2] * cvb[d2];
        float dd; sm[OFF_H1 + tid] = lipswish(acc, &dd);
    }
    __syncthreads();
    if (tid < 64){
        float acc = bi2[tid];
        #pragma unroll 8
        for (int h = 0; h < 64; h++) acc += Wi2[tid * 64 + h] * sm[OFF_H1 + h];
        sm[OFF_Y + tid] = acc;
    }
    __syncthreads();

    // ---- main Heun loop ----
    for (int n = 0; n < NW; n++){
        const float* gvec = sG + n * 36;
        // head: folded into P1 epoch (threads 128-195; no own barrier —
        // scm consumed at P4 (3 barriers later); sy stable during PH1)
        if (tid >= 128 && tid < 192){
            int t = tid - 128;
            int i = t >> 3, j = t & 7;
            float v = 0.0f;
            if (i < j) v = gvec[8 + pidx(i, j)];
            else if (i > j) v = -gvec[8 + pidx(j, i)];
            sm[OFF_CM + t] = v;
        } else if (tid >= 192 && tid < 196){
            int o = tid - 192;
            float acc = sm[OFF_BR + o] + sm[OFF_SHIFT];
            #pragma unroll 8
            for (int a = 0; a < 64; a++) acc += sm[OFF_WR + o * 64 + a] * sm[OFF_Y + a];
            out[b * (NW + 1) * OUTD + n * OUTD + o] = acc;
        }

        vf_apply<1>(tid, sm + OFF_Y,    gvec, dt);
        vf_apply<2>(tid, sm + OFF_YMID, gvec, dt);
    }

    // final readout (index NW)
    if (tid < 4){
        float acc = sm[OFF_BR + tid] + sm[OFF_SHIFT];
        #pragma unroll 8
        for (int a = 0; a < 64; a++) acc += sm[OFF_WR + tid * 64 + a] * sm[OFF_Y + a];
        out[b * (NW + 1) * OUTD + NW * OUTD + tid] = acc;
    }
}

extern "C" void kernel_launch(void* const* d_in, const int* in_sizes, int n_in,
                              void* d_out, int out_size) {
    (void)in_sizes; (void)n_in; (void)out_size;
    const size_t smem = SMEM_FLOATS * sizeof(float);  // 216,608 B
    cudaFuncSetAttribute(ncde_kernel, cudaFuncAttributeMaxDynamicSharedMemorySize, (int)smem);
    ncde_kernel<<<BD, NTH, smem>>>(
        (const float*)d_in[0],
        (const float*)d_in[1], (const float*)d_in[2],
        (const float*)d_in[3], (const float*)d_in[4],
        (const float*)d_in[5], (const float*)d_in[6],
        (const float*)d_in[7], (const float*)d_in[8],
        (const float*)d_in[9], (const float*)d_in[10],
        (const float*)d_in[11], (const float*)d_in[12],
        (const float*)d_in[13],
        (float*)d_out);
}

// round 10
// speedup vs baseline: 1.2175x; 1.1413x over previous
#include <cuda_runtime.h>
#include <cuda_fp16.h>

typedef unsigned long long u64;
typedef unsigned int u32;

#define BD   32
#define LD   513
#define DD   8
#define HD   64
#define WINW 16
#define NW   32
#define OUTD 4
#define NPAIR 28
#define NTH  512

// ---- smem layout (float offsets; all 16B-aligned) ----
// Weights packed fp16, pairs (k, k+16): uint4 chunk c holds pairs p=4c..4c+3,
// klo(c,i) = (c>>2)*32 + (c&3)*4 + i, khi = klo+16.
#define OFF_W1H  0        // uint4[8*128] : W1H[c*128+r], K=64  (pairs p<32)
#define OFF_W2H  4096     // uint4[16*128]: W2H[c*128+k], K=128 (pairs p<64)
#define OFF_W3H  12288    // uint4[16*512]: W3H[c*512+row], K=128
#define OFF_G    45056    // 1152
#define OFF_Y    46208    // 64 (f32)
#define OFF_YMID 46272    // 64 (f32)
#define OFF_K1   46336    // 64
#define OFF_CM   46400    // 64
#define OFF_S1   46464    // 128
#define OFF_S2   46592    // 128
#define OFF_F    46720    // 512
#define OFF_SP   47232    // 512
#define OFF_PART 47744    // 4096 (f32 partials; sInc staging at init)
#define OFF_YB   51840    // 32 u32  packed y
#define OFF_YMB  51872    // 32 u32  packed ymid
#define OFF_H1B  51904    // 64 u32  packed h1
#define OFF_H2B  51968    // 64 u32  packed h2
#define OFF_VPB  52032    // 256 u32 packed VpT[j][p<32]
#define OFF_D1B  52288    // 512 u32 packed D1F[j][p<64]
#define OFF_EFB  52800    // 512 u32 packed EF[j][p<64]
#define OFF_B1   53312    // 128
#define OFF_B2   53440    // 128
#define OFF_B3   53568    // 512
#define OFF_WR   54080    // 256
#define OFF_BR   54336    // 4
#define OFF_SHIFT 54340
#define SMEM_FLOATS 54344 // 217,376 B

__device__ const signed char PI_[NPAIR] = {0,0,0,0,0,0,0, 1,1,1,1,1,1, 2,2,2,2,2, 3,3,3,3, 4,4,4, 5,5, 6};
__device__ const signed char PJ_[NPAIR] = {1,2,3,4,5,6,7, 2,3,4,5,6,7, 3,4,5,6,7, 4,5,6,7, 5,6,7, 6,7, 7};

// ---------- fast math ----------
__device__ __forceinline__ float ex2f(float x){ float y; asm("ex2.approx.f32 %0, %1;" : "=f"(y) : "f"(x)); return y; }
__device__ __forceinline__ float rcpf(float x){ float y; asm("rcp.approx.f32 %0, %1;" : "=f"(y) : "f"(x)); return y; }
__device__ __forceinline__ float sigf(float x){ return rcpf(1.0f + ex2f(-1.4426950408889634f * x)); }
__device__ __forceinline__ float tanh_fast(float x){
    float t = ex2f(2.8853900817779268f * x);
    return 1.0f - 2.0f * rcpf(t + 1.0f);
}
__device__ __forceinline__ float lipswish(float x, float* dout){
    float s = sigf(x);
    *dout = 0.909f * s * fmaf(x, 1.0f - s, 1.0f);
    return 0.909f * x * s;
}

// ---------- fp16 helpers ----------
__device__ __forceinline__ __half2 u2h(u32 u){ return *reinterpret_cast<__half2*>(&u); }
__device__ __forceinline__ u32 h2u(__half2 h){ return *reinterpret_cast<u32*>(&h); }
__device__ __forceinline__ u32 pkh(float lo, float hi){ return h2u(__floats2half2_rn(lo, hi)); }
__device__ __forceinline__ float hsum2h(__half2 a, __half2 b){
    float2 fa = __half22float2(a), fb = __half22float2(b);
    return (fa.x + fa.y) + (fb.x + fb.y);
}
// 8 MACs: uint4 of half2 weights x uint4 of half2 acts into 2 half2 accumulators
__device__ __forceinline__ void q_fma(__half2& a0, __half2& a1, uint4 w, uint4 x){
    a0 = __hfma2(u2h(w.x), u2h(x.x), a0);
    a1 = __hfma2(u2h(w.y), u2h(x.y), a1);
    a0 = __hfma2(u2h(w.z), u2h(x.z), a0);
    a1 = __hfma2(u2h(w.w), u2h(x.w), a1);
}

__device__ __forceinline__ int pidx(int i, int j) { return (i * (13 - i)) / 2 + j - 1; }

extern __shared__ float sm[];

#define ZH2 (__half2(__float2half_rn(0.f), __float2half_rn(0.f)))

// PH=1: acts=yb, writes sk1/symid(+pack). PH=2: acts=ymb, updates sy(+pack).
template<int PH>
__device__ __forceinline__ void vf_apply(int tid, const float* __restrict__ gvec, float dt)
{
    const uint4* W1H = (const uint4*)(sm + OFF_W1H);
    const uint4* W2H = (const uint4*)(sm + OFF_W2H);
    const uint4* W3H = (const uint4*)(sm + OFF_W3H);
    float* ss1 = sm + OFF_S1;  float* ss2 = sm + OFF_S2;
    float* sf  = sm + OFF_F;   float* sp = sm + OFF_SP;
    float* sPart = sm + OFF_PART;
    u32* H1B = (u32*)(sm + OFF_H1B);
    u32* H2B = (u32*)(sm + OFF_H2B);
    u32* VPB = (u32*)(sm + OFF_VPB);
    u32* D1B = (u32*)(sm + OFF_D1B);
    u32* EFB = (u32*)(sm + OFF_EFB);
    const float* scm = sm + OFF_CM;

    // ---- P1: L1 forward (128 threads) ----
    if (tid < 128) {
        const int r = tid;
        const uint4* A = (const uint4*)(sm + (PH == 1 ? OFF_YB : OFF_YMB));
        __half2 a0 = ZH2, a1 = ZH2, a2 = ZH2, a3 = ZH2;
        #pragma unroll
        for (int c = 0; c < 8; c += 2){
            q_fma(a0, a1, W1H[c * 128 + r], A[c]);
            q_fma(a2, a3, W1H[(c + 1) * 128 + r], A[c + 1]);
        }
        float pre = sm[OFF_B1 + r] + hsum2h(a0, a1) + hsum2h(a2, a3);
        float d; float hv = lipswish(pre, &d); ss1[r] = d;
        float part = __shfl_xor_sync(0xffffffffu, hv, 16);
        if (!(r & 16)) H1B[((r >> 5) << 4) | (r & 15)] = pkh(hv, part);
    }
    __syncthreads();

    // ---- P2: L2 forward (128 threads) ----
    if (tid < 128) {
        const int k = tid;
        const uint4* A = (const uint4*)H1B;
        __half2 a0 = ZH2, a1 = ZH2, a2 = ZH2, a3 = ZH2;
        #pragma unroll 4
        for (int c = 0; c < 16; c += 2){
            q_fma(a0, a1, W2H[c * 128 + k], A[c]);
            q_fma(a2, a3, W2H[(c + 1) * 128 + k], A[c + 1]);
        }
        float pre = sm[OFF_B2 + k] + hsum2h(a0, a1) + hsum2h(a2, a3);
        float d; float hv = lipswish(pre, &d); ss2[k] = d;
        float part = __shfl_xor_sync(0xffffffffu, hv, 16);
        if (!(k & 16)) H2B[((k >> 5) << 4) | (k & 15)] = pkh(hv, part);
    }
    __syncthreads();

    // ---- P3: L3 forward (512 threads, row = tid, K=128) ----
    {
        const int row = tid;
        const uint4* A = (const uint4*)H2B;
        __half2 a0 = ZH2, a1 = ZH2, a2 = ZH2, a3 = ZH2;
        #pragma unroll 4
        for (int c = 0; c < 16; c += 2){
            q_fma(a0, a1, W3H[c * 512 + row], A[c]);
            q_fma(a2, a3, W3H[(c + 1) * 512 + row], A[c + 1]);
        }
        sf[row] = tanh_fast(sm[OFF_B3 + row] + hsum2h(a0, a1) + hsum2h(a2, a3));
    }
    __syncthreads();

    // ---- P4: VpT[j][b] + pack (512 threads) ----
    {
        const int j = tid >> 6, bq = tid & 63;
        float acc = 0.f;
        #pragma unroll
        for (int i = 0; i < 8; i++) acc += sf[i * 64 + bq] * scm[i * 8 + j];
        float part = __shfl_xor_sync(0xffffffffu, acc, 16);
        if (!(bq & 16)) VPB[j * 32 + (((bq >> 5) << 4) | (bq & 15))] = pkh(acc, part);
    }
    __syncthreads();

    // ---- P5: U1' (512 threads; r = tid&127, jg = tid>>7: j = jg, jg+4) ----
    {
        const int r = tid & 127, jg = tid >> 7;
        const uint4* A0 = (const uint4*)(VPB + jg * 32);
        const uint4* A1 = (const uint4*)(VPB + (jg + 4) * 32);
        __half2 a00 = ZH2, a01 = ZH2, a10 = ZH2, a11 = ZH2;
        #pragma unroll
        for (int c = 0; c < 8; c++){
            uint4 w = W1H[c * 128 + r];
            q_fma(a00, a01, w, A0[c]);
            q_fma(a10, a11, w, A1[c]);
        }
        const float s = ss1[r];
        float v0 = s * hsum2h(a00, a01);
        float v1 = s * hsum2h(a10, a11);
        float p0 = __shfl_xor_sync(0xffffffffu, v0, 16);
        float p1 = __shfl_xor_sync(0xffffffffu, v1, 16);
        if (!(r & 16)){
            int pr = ((r >> 5) << 4) | (r & 15);
            D1B[jg * 64 + pr]       = pkh(v0, p0);
            D1B[(jg + 4) * 64 + pr] = pkh(v1, p1);
        }
    }
    __syncthreads();

    // ---- P6p: U2' partials (512 threads; cc = chunk over r-pairs, k = tid&127) ----
    {
        const int cc = tid >> 7, k = tid & 127;
        __half2 acc[8] = {ZH2,ZH2,ZH2,ZH2,ZH2,ZH2,ZH2,ZH2};
        #pragma unroll
        for (int ir = 0; ir < 4; ir++){
            const int c = 4 * cc + ir;
            uint4 w = W2H[c * 128 + k];
            #pragma unroll
            for (int j = 0; j < 8; j++){
                uint4 x = *(const uint4*)(D1B + j * 64 + 4 * c);
                acc[j] = __hfma2(u2h(w.x), u2h(x.x), acc[j]);
                acc[j] = __hfma2(u2h(w.y), u2h(x.y), acc[j]);
                acc[j] = __hfma2(u2h(w.z), u2h(x.z), acc[j]);
                acc[j] = __hfma2(u2h(w.w), u2h(x.w), acc[j]);
            }
        }
        #pragma unroll
        for (int j = 0; j < 8; j++){
            float2 f = __half22float2(acc[j]);
            sPart[cc * 1024 + j * 128 + k] = f.x + f.y;
        }
    }
    __syncthreads();

    // ---- P6b: U2' reduce -> pack EF (512 threads) ----
    {
        const int jg = tid >> 7, k = tid & 127;
        const float s = ss2[k];
        #pragma unroll
        for (int jj = jg; jj < 8; jj += 4){
            float v = s * (sPart[jj * 128 + k] + sPart[1024 + jj * 128 + k]
                         + sPart[2048 + jj * 128 + k] + sPart[3072 + jj * 128 + k]);
            float part = __shfl_xor_sync(0xffffffffu, v, 16);
            if (!(k & 16)) EFB[jj * 64 + (((k >> 5) << 4) | (k & 15))] = pkh(v, part);
        }
    }
    __syncthreads();

    // ---- P7: diag + folded g-term (row = tid, j = row>>6, K=128) ----
    {
        const int row = tid, j = row >> 6;
        const uint4* A = (const uint4*)(EFB + j * 64);
        __half2 a0 = ZH2, a1 = ZH2, a2 = ZH2, a3 = ZH2;
        #pragma unroll 4
        for (int c = 0; c < 16; c += 2){
            q_fma(a0, a1, W3H[c * 512 + row], A[c]);
            q_fma(a2, a3, W3H[(c + 1) * 512 + row], A[c + 1]);
        }
        float f = sf[row];
        sp[row] = (1.0f - f * f) * (hsum2h(a0, a1) + hsum2h(a2, a3)) + gvec[j] * f;
    }
    __syncthreads();

    // ---- P8: combine + Heun update + pack (64 threads) ----
    if (tid < 64){
        float acc = 0.f;
        #pragma unroll
        for (int j = 0; j < 8; j++) acc += sp[j * 64 + tid];
        if (PH == 1){
            sm[OFF_K1 + tid] = acc;
            float ym = sm[OFF_Y + tid] + dt * acc;
            sm[OFF_YMID + tid] = ym;
            float part = __shfl_xor_sync(0xffffffffu, ym, 16);
            if (!(tid & 16)) ((u32*)(sm + OFF_YMB))[((tid >> 5) << 4) | (tid & 15)] = pkh(ym, part);
        } else {
            float yn = sm[OFF_Y + tid] + 0.5f * dt * (sm[OFF_K1 + tid] + acc);
            sm[OFF_Y + tid] = yn;
            float part = __shfl_xor_sync(0xffffffffu, yn, 16);
            if (!(tid & 16)) ((u32*)(sm + OFF_YB))[((tid >> 5) << 4) | (tid & 15)] = pkh(yn, part);
        }
    }
    __syncthreads();
}

__global__ void __launch_bounds__(NTH, 1) ncde_kernel(
    const float* __restrict__ cv,
    const float* __restrict__ Wi1, const float* __restrict__ bi1,
    const float* __restrict__ Wi2, const float* __restrict__ bi2,
    const float* __restrict__ W1, const float* __restrict__ b1,
    const float* __restrict__ W2, const float* __restrict__ b2,
    const float* __restrict__ W3, const float* __restrict__ b3,
    const float* __restrict__ Wr, const float* __restrict__ br,
    const float* __restrict__ shiftp,
    float* __restrict__ out)
{
    const int tid = threadIdx.x;
    const int b = blockIdx.x;

    const float dt = (float)WINW / (float)(LD - 1);
    const float inv_dt = 1.0f / dt;

    float* sG = sm + OFF_G;
    float* sInc = sm + OFF_PART;

    // ---- init: pack weights fp16 pairs (k, k+16) ----
    {
        u32* W1Hu = (u32*)(sm + OFF_W1H);
        for (int idx = tid; idx < 8 * 128; idx += NTH){
            int c = idx >> 7, r = idx & 127;
            int base = (c >> 2) * 32 + (c & 3) * 4;
            u32* dst = W1Hu + idx * 4;
            #pragma unroll
            for (int i = 0; i < 4; i++){
                int klo = base + i;
                dst[i] = pkh(W1[r * 64 + klo], W1[r * 64 + klo + 16]);
            }
        }
        u32* W2Hu = (u32*)(sm + OFF_W2H);
        for (int idx = tid; idx < 16 * 128; idx += NTH){
            int c = idx >> 7, k = idx & 127;
            int base = (c >> 2) * 32 + (c & 3) * 4;
            u32* dst = W2Hu + idx * 4;
            #pragma unroll
            for (int i = 0; i < 4; i++){
                int klo = base + i;
                dst[i] = pkh(W2[k * 128 + klo], W2[k * 128 + klo + 16]);
            }
        }
        u32* W3Hu = (u32*)(sm + OFF_W3H);
        for (int idx = tid; idx < 16 * 512; idx += NTH){
            int c = idx >> 9, row = idx & 511;
            int base = (c >> 2) * 32 + (c & 3) * 4;
            u32* dst = W3Hu + (c * 512 + row) * 4;
            #pragma unroll
            for (int i = 0; i < 4; i++){
                int klo = base + i;
                dst[i] = pkh(W3[row * 128 + klo], W3[row * 128 + klo + 16]);
            }
        }
    }
    const float* cvb = cv + (size_t)b * LD * DD;
    for (int idx = tid; idx < 512 * 8; idx += NTH){
        sInc[idx] = cvb[idx + 8] - cvb[idx];
    }
    if (tid < 128) sm[OFF_B1 + tid] = b1[tid];
    else if (tid < 256) sm[OFF_B2 + tid - 128] = b2[tid - 128];
    else if (tid < 260) sm[OFF_BR + tid - 256] = br[tid - 256];
    else if (tid == 260) sm[OFF_SHIFT] = *shiftp;
    for (int idx = tid; idx < 512; idx += NTH) sm[OFF_B3 + idx] = b3[idx];
    for (int idx = tid; idx < 256; idx += NTH) sm[OFF_WR + idx] = Wr[idx];
    __syncthreads();

    // ---- window log-signatures (pre-divided by dt) + y0 layer 1 ----
    for (int idx = tid; idx < NW * NPAIR; idx += NTH){
        int w = idx / NPAIR, p = idx % NPAIR;
        int i = PI_[p], j = PJ_[p];
        float acc = 0.f, pi = 0.f, pj = 0.f;
        const float* base = sInc + w * 16 * 8;
        #pragma unroll
        for (int s = 0; s < 16; s++){
            float ii = base[s * 8 + i], jj = base[s * 8 + j];
            acc += pi * jj - pj * ii;
            pi += ii; pj += jj;
        }
        sG[w * 36 + 8 + p] = 0.5f * acc * inv_dt;
    }
    for (int idx = tid; idx < NW * 8; idx += NTH){
        int w = idx >> 3, d2 = idx & 7;
        sG[w * 36 + d2] = (cvb[(16 * w + 16) * 8 + d2] - cvb[16 * w * 8 + d2]) * inv_dt;
    }
    if (tid < 64){
        float acc = bi1[tid];
        #pragma unroll
        for (int d2 = 0; d2 < 8; d2++) acc += Wi1[tid * 8 + d2] * cvb[d2];
        float dd; sm[OFF_SP + tid] = lipswish(acc, &dd);   // temp in sp
    }
    __syncthreads();
    if (tid < 64){
        float acc = bi2[tid];
        #pragma unroll 8
        for (int h = 0; h < 64; h++) acc += Wi2[tid * 64 + h] * sm[OFF_SP + h];
        sm[OFF_Y + tid] = acc;
        float part = __shfl_xor_sync(0xffffffffu, acc, 16);
        if (!(tid & 16)) ((u32*)(sm + OFF_YB))[((tid >> 5) << 4) | (tid & 15)] = pkh(acc, part);
    }
    __syncthreads();

    // ---- main Heun loop ----
    for (int n = 0; n < NW; n++){
        const float* gvec = sG + n * 36;
        // head folded into P1 epoch (threads 128-195; scm consumed at P4)
        if (tid >= 128 && tid < 192){
            int t = tid - 128;
            int i = t >> 3, j = t & 7;
            float v = 0.0f;
            if (i < j) v = gvec[8 + pidx(i, j)];
            else if (i > j) v = -gvec[8 + pidx(j, i)];
            sm[OFF_CM + t] = v;
        } else if (tid >= 192 && tid < 196){
            int o = tid - 192;
            float acc = sm[OFF_BR + o] + sm[OFF_SHIFT];
            #pragma unroll 8
            for (int a = 0; a < 64; a++) acc += sm[OFF_WR + o * 64 + a] * sm[OFF_Y + a];
            out[b * (NW + 1) * OUTD + n * OUTD + o] = acc;
        }

        vf_apply<1>(tid, gvec, dt);
        vf_apply<2>(tid, gvec, dt);
    }

    // final readout (index NW)
    if (tid < 4){
        float acc = sm[OFF_BR + tid] + sm[OFF_SHIFT];
        #pragma unroll 8
        for (int a = 0; a < 64; a++) acc += sm[OFF_WR + tid * 64 + a] * sm[OFF_Y + a];
        out[b * (NW + 1) * OUTD + NW * OUTD + tid] = acc;
    }
}

extern "C" void kernel_launch(void* const* d_in, const int* in_sizes, int n_in,
                              void* d_out, int out_size) {
    (void)in_sizes; (void)n_in; (void)out_size;
    const size_t smem = SMEM_FLOATS * sizeof(float);  // 217,376 B
    cudaFuncSetAttribute(ncde_kernel, cudaFuncAttributeMaxDynamicSharedMemorySize, (int)smem);
    ncde_kernel<<<BD, NTH, smem>>>(
        (const float*)d_in[0],
        (const float*)d_in[1], (const float*)d_in[2],
        (const float*)d_in[3], (const float*)d_in[4],
        (const float*)d_in[5], (const float*)d_in[6],
        (const float*)d_in[7], (const float*)d_in[8],
        (const float*)d_in[9], (const float*)d_in[10],
        (const float*)d_in[11], (const float*)d_in[12],
        (const float*)d_in[13],
        (float*)d_out);
}

// round 11
// speedup vs baseline: 1.5094x; 1.2398x over previous
#include <cuda_runtime.h>
#include <cuda_fp16.h>

typedef unsigned long long u64;
typedef unsigned int u32;

#define BD   32
#define LD   513
#define DD   8
#define HD   64
#define WINW 16
#define NW   32
#define OUTD 4
#define NPAIR 28
#define NTH  512

// ---- smem layout (float offsets; all 16B-aligned). W3 lives in REGISTERS. ----
// Weights packed fp16, pairs (k, k+16): uint4 chunk c holds pairs p=4c..4c+3,
// klo(c,i) = (c>>2)*32 + (c&3)*4 + i, khi = klo+16.
#define OFF_W1H  0        // uint4[8*128] : W1H[c*128+r], K=64
#define OFF_W2H  4096     // uint4[16*128]: W2H[c*128+k], K=128
#define OFF_G    12288    // 1152
#define OFF_Y    13440    // 64 (f32)
#define OFF_YMID 13504    // 64 (f32)
#define OFF_K1   13568    // 64
#define OFF_CM   13632    // 64
#define OFF_S1   13696    // 128
#define OFF_S2   13824    // 128
#define OFF_F    13952    // 512
#define OFF_SP   14464    // 512
#define OFF_PART 14976    // 4096 (f32 partials; sInc staging at init)
#define OFF_YB   19072    // 32 u32  packed y
#define OFF_YMB  19104    // 32 u32  packed ymid
#define OFF_H1B  19136    // 64 u32  packed h1
#define OFF_H2B  19200    // 64 u32  packed h2
#define OFF_VPB  19264    // 256 u32 packed VpT
#define OFF_D1B  19520    // 512 u32 packed D1F
#define OFF_EFB  20032    // 512 u32 packed EF
#define OFF_B1   20544    // 128
#define OFF_B2   20672    // 128
#define OFF_B3   20800    // 512
#define OFF_WR   21312    // 256
#define OFF_BR   21568    // 4
#define OFF_SHIFT 21572
#define SMEM_FLOATS 21576 // 86,304 B

__device__ const signed char PI_[NPAIR] = {0,0,0,0,0,0,0, 1,1,1,1,1,1, 2,2,2,2,2, 3,3,3,3, 4,4,4, 5,5, 6};
__device__ const signed char PJ_[NPAIR] = {1,2,3,4,5,6,7, 2,3,4,5,6,7, 3,4,5,6,7, 4,5,6,7, 5,6,7, 6,7, 7};

// ---------- fast math ----------
__device__ __forceinline__ float ex2f(float x){ float y; asm("ex2.approx.f32 %0, %1;" : "=f"(y) : "f"(x)); return y; }
__device__ __forceinline__ float rcpf(float x){ float y; asm("rcp.approx.f32 %0, %1;" : "=f"(y) : "f"(x)); return y; }
__device__ __forceinline__ float sigf(float x){ return rcpf(1.0f + ex2f(-1.4426950408889634f * x)); }
__device__ __forceinline__ float tanh_fast(float x){
    float t = ex2f(2.8853900817779268f * x);
    return 1.0f - 2.0f * rcpf(t + 1.0f);
}
__device__ __forceinline__ float lipswish(float x, float* dout){
    float s = sigf(x);
    *dout = 0.909f * s * fmaf(x, 1.0f - s, 1.0f);
    return 0.909f * x * s;
}

// ---------- fp16 helpers ----------
__device__ __forceinline__ __half2 u2h(u32 u){ return *reinterpret_cast<__half2*>(&u); }
__device__ __forceinline__ u32 h2u(__half2 h){ return *reinterpret_cast<u32*>(&h); }
__device__ __forceinline__ u32 pkh(float lo, float hi){ return h2u(__floats2half2_rn(lo, hi)); }
__device__ __forceinline__ float hsum2h(__half2 a, __half2 b){
    float2 fa = __half22float2(a), fb = __half22float2(b);
    return (fa.x + fa.y) + (fb.x + fb.y);
}
// 8 MACs: uint4 of half2 weights x uint4 of half2 acts into 2 half2 accumulators
__device__ __forceinline__ void q_fma(__half2& a0, __half2& a1, uint4 w, uint4 x){
    a0 = __hfma2(u2h(w.x), u2h(x.x), a0);
    a1 = __hfma2(u2h(w.y), u2h(x.y), a1);
    a0 = __hfma2(u2h(w.z), u2h(x.z), a0);
    a1 = __hfma2(u2h(w.w), u2h(x.w), a1);
}

__device__ __forceinline__ int pidx(int i, int j) { return (i * (13 - i)) / 2 + j - 1; }

extern __shared__ float sm[];

#define ZH2 (__half2(__float2half_rn(0.f), __float2half_rn(0.f)))

// PH=1: acts=yb, writes sk1/symid(+pack). PH=2: acts=ymb, updates sy(+pack).
// w3r = this thread's W3 row (row index = tid), 16 uint4 in registers.
template<int PH>
__device__ __forceinline__ void vf_apply(int tid, const uint4* __restrict__ w3r,
                                         const float* __restrict__ gvec, float dt)
{
    const uint4* W1H = (const uint4*)(sm + OFF_W1H);
    const uint4* W2H = (const uint4*)(sm + OFF_W2H);
    float* ss1 = sm + OFF_S1;  float* ss2 = sm + OFF_S2;
    float* sf  = sm + OFF_F;   float* sp = sm + OFF_SP;
    float* sPart = sm + OFF_PART;
    u32* H1B = (u32*)(sm + OFF_H1B);
    u32* H2B = (u32*)(sm + OFF_H2B);
    u32* VPB = (u32*)(sm + OFF_VPB);
    u32* D1B = (u32*)(sm + OFF_D1B);
    u32* EFB = (u32*)(sm + OFF_EFB);
    const float* scm = sm + OFF_CM;

    // ---- P1: L1 forward (128 threads) ----
    if (tid < 128) {
        const int r = tid;
        const uint4* A = (const uint4*)(sm + (PH == 1 ? OFF_YB : OFF_YMB));
        __half2 a0 = ZH2, a1 = ZH2, a2 = ZH2, a3 = ZH2;
        #pragma unroll
        for (int c = 0; c < 8; c += 2){
            q_fma(a0, a1, W1H[c * 128 + r], A[c]);
            q_fma(a2, a3, W1H[(c + 1) * 128 + r], A[c + 1]);
        }
        float pre = sm[OFF_B1 + r] + hsum2h(a0, a1) + hsum2h(a2, a3);
        float d; float hv = lipswish(pre, &d); ss1[r] = d;
        float part = __shfl_xor_sync(0xffffffffu, hv, 16);
        if (!(r & 16)) H1B[((r >> 5) << 4) | (r & 15)] = pkh(hv, part);
    }
    __syncthreads();

    // ---- P2: L2 forward (128 threads) ----
    if (tid < 128) {
        const int k = tid;
        const uint4* A = (const uint4*)H1B;
        __half2 a0 = ZH2, a1 = ZH2, a2 = ZH2, a3 = ZH2;
        #pragma unroll 4
        for (int c = 0; c < 16; c += 2){
            q_fma(a0, a1, W2H[c * 128 + k], A[c]);
            q_fma(a2, a3, W2H[(c + 1) * 128 + k], A[c + 1]);
        }
        float pre = sm[OFF_B2 + k] + hsum2h(a0, a1) + hsum2h(a2, a3);
        float d; float hv = lipswish(pre, &d); ss2[k] = d;
        float part = __shfl_xor_sync(0xffffffffu, hv, 16);
        if (!(k & 16)) H2B[((k >> 5) << 4) | (k & 15)] = pkh(hv, part);
    }
    __syncthreads();

    // ---- P3: L3 forward (512 threads, row = tid, K=128; weights in regs) ----
    {
        const uint4* A = (const uint4*)H2B;
        __half2 a0 = ZH2, a1 = ZH2, a2 = ZH2, a3 = ZH2;
        #pragma unroll
        for (int c = 0; c < 16; c += 2){
            q_fma(a0, a1, w3r[c], A[c]);
            q_fma(a2, a3, w3r[c + 1], A[c + 1]);
        }
        sf[tid] = tanh_fast(sm[OFF_B3 + tid] + hsum2h(a0, a1) + hsum2h(a2, a3));
    }
    __syncthreads();

    // ---- P4: VpT[j][b] + pack (512 threads) ----
    {
        const int j = tid >> 6, bq = tid & 63;
        float acc = 0.f;
        #pragma unroll
        for (int i = 0; i < 8; i++) acc += sf[i * 64 + bq] * scm[i * 8 + j];
        float part = __shfl_xor_sync(0xffffffffu, acc, 16);
        if (!(bq & 16)) VPB[j * 32 + (((bq >> 5) << 4) | (bq & 15))] = pkh(acc, part);
    }
    __syncthreads();

    // ---- P5: U1' (512 threads; r = tid&127, jg = tid>>7: j = jg, jg+4) ----
    {
        const int r = tid & 127, jg = tid >> 7;
        const uint4* A0 = (const uint4*)(VPB + jg * 32);
        const uint4* A1 = (const uint4*)(VPB + (jg + 4) * 32);
        __half2 a00 = ZH2, a01 = ZH2, a10 = ZH2, a11 = ZH2;
        #pragma unroll
        for (int c = 0; c < 8; c++){
            uint4 w = W1H[c * 128 + r];
            q_fma(a00, a01, w, A0[c]);
            q_fma(a10, a11, w, A1[c]);
        }
        const float s = ss1[r];
        float v0 = s * hsum2h(a00, a01);
        float v1 = s * hsum2h(a10, a11);
        float p0 = __shfl_xor_sync(0xffffffffu, v0, 16);
        float p1 = __shfl_xor_sync(0xffffffffu, v1, 16);
        if (!(r & 16)){
            int pr = ((r >> 5) << 4) | (r & 15);
            D1B[jg * 64 + pr]       = pkh(v0, p0);
            D1B[(jg + 4) * 64 + pr] = pkh(v1, p1);
        }
    }
    __syncthreads();

    // ---- P6p: U2' partials (512 threads; cc = chunk over r-pairs, k = tid&127) ----
    {
        const int cc = tid >> 7, k = tid & 127;
        __half2 acc[8] = {ZH2,ZH2,ZH2,ZH2,ZH2,ZH2,ZH2,ZH2};
        #pragma unroll
        for (int ir = 0; ir < 4; ir++){
            const int c = 4 * cc + ir;
            uint4 w = W2H[c * 128 + k];
            #pragma unroll
            for (int j = 0; j < 8; j++){
                uint4 x = *(const uint4*)(D1B + j * 64 + 4 * c);
                acc[j] = __hfma2(u2h(w.x), u2h(x.x), acc[j]);
                acc[j] = __hfma2(u2h(w.y), u2h(x.y), acc[j]);
                acc[j] = __hfma2(u2h(w.z), u2h(x.z), acc[j]);
                acc[j] = __hfma2(u2h(w.w), u2h(x.w), acc[j]);
            }
        }
        #pragma unroll
        for (int j = 0; j < 8; j++){
            float2 f = __half22float2(acc[j]);
            sPart[cc * 1024 + j * 128 + k] = f.x + f.y;
        }
    }
    __syncthreads();

    // ---- P6b: U2' reduce -> pack EF (512 threads) ----
    {
        const int jg = tid >> 7, k = tid & 127;
        const float s = ss2[k];
        #pragma unroll
        for (int jj = jg; jj < 8; jj += 4){
            float v = s * (sPart[jj * 128 + k] + sPart[1024 + jj * 128 + k]
                         + sPart[2048 + jj * 128 + k] + sPart[3072 + jj * 128 + k]);
            float part = __shfl_xor_sync(0xffffffffu, v, 16);
            if (!(k & 16)) EFB[jj * 64 + (((k >> 5) << 4) | (k & 15))] = pkh(v, part);
        }
    }
    __syncthreads();

    // ---- P7: diag + folded g-term (row = tid, j = row>>6; weights in regs) ----
    {
        const int j = tid >> 6;
        const uint4* A = (const uint4*)(EFB + j * 64);
        __half2 a0 = ZH2, a1 = ZH2, a2 = ZH2, a3 = ZH2;
        #pragma unroll
        for (int c = 0; c < 16; c += 2){
            q_fma(a0, a1, w3r[c], A[c]);
            q_fma(a2, a3, w3r[c + 1], A[c + 1]);
        }
        float f = sf[tid];
        sp[tid] = (1.0f - f * f) * (hsum2h(a0, a1) + hsum2h(a2, a3)) + gvec[j] * f;
    }
    __syncthreads();

    // ---- P8: combine + Heun update + pack (64 threads) ----
    if (tid < 64){
        float acc = 0.f;
        #pragma unroll
        for (int j = 0; j < 8; j++) acc += sp[j * 64 + tid];
        if (PH == 1){
            sm[OFF_K1 + tid] = acc;
            float ym = sm[OFF_Y + tid] + dt * acc;
            sm[OFF_YMID + tid] = ym;
            float part = __shfl_xor_sync(0xffffffffu, ym, 16);
            if (!(tid & 16)) ((u32*)(sm + OFF_YMB))[((tid >> 5) << 4) | (tid & 15)] = pkh(ym, part);
        } else {
            float yn = sm[OFF_Y + tid] + 0.5f * dt * (sm[OFF_K1 + tid] + acc);
            sm[OFF_Y + tid] = yn;
            float part = __shfl_xor_sync(0xffffffffu, yn, 16);
            if (!(tid & 16)) ((u32*)(sm + OFF_YB))[((tid >> 5) << 4) | (tid & 15)] = pkh(yn, part);
        }
    }
    __syncthreads();
}

__global__ void __launch_bounds__(NTH, 1) ncde_kernel(
    const float* __restrict__ cv,
    const float* __restrict__ Wi1, const float* __restrict__ bi1,
    const float* __restrict__ Wi2, const float* __restrict__ bi2,
    const float* __restrict__ W1, const float* __restrict__ b1,
    const float* __restrict__ W2, const float* __restrict__ b2,
    const float* __restrict__ W3, const float* __restrict__ b3,
    const float* __restrict__ Wr, const float* __restrict__ br,
    const float* __restrict__ shiftp,
    float* __restrict__ out)
{
    const int tid = threadIdx.x;
    const int b = blockIdx.x;

    const float dt = (float)WINW / (float)(LD - 1);
    const float inv_dt = 1.0f / dt;

    float* sG = sm + OFF_G;
    float* sInc = sm + OFF_PART;

    // ---- W3 row -> registers (pairs (k, k+16), same chunk scheme as smem weights) ----
    uint4 w3r[16];
    {
        const float* row = W3 + tid * 128;
        #pragma unroll
        for (int c = 0; c < 16; c++){
            int base = (c >> 2) * 32 + (c & 3) * 4;
            w3r[c].x = pkh(row[base + 0], row[base + 16]);
            w3r[c].y = pkh(row[base + 1], row[base + 17]);
            w3r[c].z = pkh(row[base + 2], row[base + 18]);
            w3r[c].w = pkh(row[base + 3], row[base + 19]);
        }
    }

    // ---- init: pack W1/W2 fp16 pairs (k, k+16) into smem ----
    {
        u32* W1Hu = (u32*)(sm + OFF_W1H);
        for (int idx = tid; idx < 8 * 128; idx += NTH){
            int c = idx >> 7, r = idx & 127;
            int base = (c >> 2) * 32 + (c & 3) * 4;
            u32* dst = W1Hu + idx * 4;
            #pragma unroll
            for (int i = 0; i < 4; i++){
                int klo = base + i;
                dst[i] = pkh(W1[r * 64 + klo], W1[r * 64 + klo + 16]);
            }
        }
        u32* W2Hu = (u32*)(sm + OFF_W2H);
        for (int idx = tid; idx < 16 * 128; idx += NTH){
            int c = idx >> 7, k = idx & 127;
            int base = (c >> 2) * 32 + (c & 3) * 4;
            u32* dst = W2Hu + idx * 4;
            #pragma unroll
            for (int i = 0; i < 4; i++){
                int klo = base + i;
                dst[i] = pkh(W2[k * 128 + klo], W2[k * 128 + klo + 16]);
            }
        }
    }
    const float* cvb = cv + (size_t)b * LD * DD;
    for (int idx = tid; idx < 512 * 8; idx += NTH){
        sInc[idx] = cvb[idx + 8] - cvb[idx];
    }
    if (tid < 128) sm[OFF_B1 + tid] = b1[tid];
    else if (tid < 256) sm[OFF_B2 + tid - 128] = b2[tid - 128];
    else if (tid < 260) sm[OFF_BR + tid - 256] = br[tid - 256];
    else if (tid == 260) sm[OFF_SHIFT] = *shiftp;
    for (int idx = tid; idx < 512; idx += NTH) sm[OFF_B3 + idx] = b3[idx];
    for (int idx = tid; idx < 256; idx += NTH) sm[OFF_WR + idx] = Wr[idx];
    __syncthreads();

    // ---- window log-signatures (pre-divided by dt) + y0 layer 1 ----
    for (int idx = tid; idx < NW * NPAIR; idx += NTH){
        int w = idx / NPAIR, p = idx % NPAIR;
        int i = PI_[p], j = PJ_[p];
        float acc = 0.f, pi = 0.f, pj = 0.f;
        const float* base = sInc + w * 16 * 8;
        #pragma unroll
        for (int s = 0; s < 16; s++){
            float ii = base[s * 8 + i], jj = base[s * 8 + j];
            acc += pi * jj - pj * ii;
            pi += ii; pj += jj;
        }
        sG[w * 36 + 8 + p] = 0.5f * acc * inv_dt;
    }
    for (int idx = tid; idx < NW * 8; idx += NTH){
        int w = idx >> 3, d2 = idx & 7;
        sG[w * 36 + d2] = (cvb[(16 * w + 16) * 8 + d2] - cvb[16 * w * 8 + d2]) * inv_dt;
    }
    if (tid < 64){
        float acc = bi1[tid];
        #pragma unroll
        for (int d2 = 0; d2 < 8; d2++) acc += Wi1[tid * 8 + d2] * cvb[d2];
        float dd; sm[OFF_SP + tid] = lipswish(acc, &dd);   // temp in sp
    }
    __syncthreads();
    if (tid < 64){
        float acc = bi2[tid];
        #pragma unroll 8
        for (int h = 0; h < 64; h++) acc += Wi2[tid * 64 + h] * sm[OFF_SP + h];
        sm[OFF_Y + tid] = acc;
        float part = __shfl_xor_sync(0xffffffffu, acc, 16);
        if (!(tid & 16)) ((u32*)(sm + OFF_YB))[((tid >> 5) << 4) | (tid & 15)] = pkh(acc, part);
    }
    __syncthreads();

    // ---- main Heun loop ----
    for (int n = 0; n < NW; n++){
        const float* gvec = sG + n * 36;
        // head folded into P1 epoch (threads 128-195; scm consumed at P4)
        if (tid >= 128 && tid < 192){
            int t = tid - 128;
            int i = t >> 3, j = t & 7;
            float v = 0.0f;
            if (i < j) v = gvec[8 + pidx(i, j)];
            else if (i > j) v = -gvec[8 + pidx(j, i)];
            sm[OFF_CM + t] = v;
        } else if (tid >= 192 && tid < 196){
            int o = tid - 192;
            float acc = sm[OFF_BR + o] + sm[OFF_SHIFT];
            #pragma unroll 8
            for (int a = 0; a < 64; a++) acc += sm[OFF_WR + o * 64 + a] * sm[OFF_Y + a];
            out[b * (NW + 1) * OUTD + n * OUTD + o] = acc;
        }

        vf_apply<1>(tid, w3r, gvec, dt);
        vf_apply<2>(tid, w3r, gvec, dt);
    }

    // final readout (index NW)
    if (tid < 4){
        float acc = sm[OFF_BR + tid] + sm[OFF_SHIFT];
        #pragma unroll 8
        for (int a = 0; a < 64; a++) acc += sm[OFF_WR + tid * 64 + a] * sm[OFF_Y + a];
        out[b * (NW + 1) * OUTD + NW * OUTD + tid] = acc;
    }
}

extern "C" void kernel_launch(void* const* d_in, const int* in_sizes, int n_in,
                              void* d_out, int out_size) {
    (void)in_sizes; (void)n_in; (void)out_size;
    const size_t smem = SMEM_FLOATS * sizeof(float);  // 86,304 B
    cudaFuncSetAttribute(ncde_kernel, cudaFuncAttributeMaxDynamicSharedMemorySize, (int)smem);
    ncde_kernel<<<BD, NTH, smem>>>(
        (const float*)d_in[0],
        (const float*)d_in[1], (const float*)d_in[2],
        (const float*)d_in[3], (const float*)d_in[4],
        (const float*)d_in[5], (const float*)d_in[6],
        (const float*)d_in[7], (const float*)d_in[8],
        (const float*)d_in[9], (const float*)d_in[10],
        (const float*)d_in[11], (const float*)d_in[12],
        (const float*)d_in[13],
        (float*)d_out);
}